// round 9
// baseline (speedup 1.0000x reference)
#include <cuda_runtime.h>
#include <math.h>

#define N_PROP 1000
#define NUM_CLASSES 81
#define NUM_FG 80
#define SCORE_THRESH 0.05f
#define NMS_THRESH 0.5f
#define DET_PER_IMG 100
#define BBOX_XFORM_CLIP 4.135166556742356f
#define CAND_MAX (N_PROP * NUM_FG)

#define NBLOCKS 80
#define NTHREADS 256

#define PROB_PITCH 1024      // padded row pitch for transposed probs

#define MROW 1024            // global-mask rows (fallback, M <= 1000)
#define MWORDS 32            // 1024 bits
#define MROW_SH 256          // shared-mask rows (fast path)
#define MWORDS_SH 8          // 256 bits

#define NBINS 4096
#define TOPK_CAP 2048

typedef unsigned long long u64;
typedef unsigned int u32;

// ---------- device scratch (no allocations allowed) ----------
__device__ float  g_probT[NUM_CLASSES * PROB_PITCH];   // [class][proposal]
__device__ int    g_count;
__device__ float  g_cscore[CAND_MAX];
__device__ int    g_ckey[CAND_MAX];
__device__ float4 g_boxkey[CAND_MAX];
__device__ u32    g_mask[NUM_FG * MROW * MWORDS];      // fallback mask (M > 256)

// self-resetting grid barrier state (gen is monotonic across graph replays)
__device__ unsigned int g_bar_count = 0;
__device__ unsigned int g_bar_gen   = 0;

__device__ __forceinline__ void grid_sync() {
    __threadfence();
    __syncthreads();
    if (threadIdx.x == 0) {
        unsigned gen = *((volatile unsigned*)&g_bar_gen);
        unsigned old = atomicInc(&g_bar_count, NBLOCKS - 1);   // wraps to 0 -> self-reset
        if (old == NBLOCKS - 1) {
            atomicAdd(&g_bar_gen, 1);
        } else {
            while (*((volatile unsigned*)&g_bar_gen) == gen) {}
        }
    }
    __syncthreads();
    __threadfence();
}

__device__ __forceinline__ float load_dim(const int* p) {
    int vi = *p;
    if (vi > 0 && vi < 100000) return (float)vi;
    return __int_as_float(vi);
}

__device__ __forceinline__ int score_bin(u32 bits) {
    int b = (int)(bits >> 14) - 0xF400;      // scores in (0.05, 1] -> positive bins
    return min(NBINS - 1, max(0, b));
}

// ---------- shared memory union across phases ----------
struct SmemNMS {
    u64    key[1024];        // (score_bits<<32) | ~prop_idx
    float4 box[1024];
    u32    masksh[MROW_SH * MWORDS_SH];
    u32    keepw[MWORDS];
    int    wpfx[MWORDS + 1]; // popcount prefix of keepw
    int    base;
    int    cnt;
};
struct SmemTopk {
    u64 buf[TOPK_CAP];
    int hist[NBINS];
    int part[NTHREADS];
    int bstar;
    int cnt;
};
union SmemAll {
    SmemNMS  nms;
    SmemTopk topk;
};

__global__ void __launch_bounds__(NTHREADS, 1)
fused_kernel(const float* __restrict__ logits,
             const float* __restrict__ deltas,
             const float* __restrict__ pboxes,
             const int* __restrict__ ih_p,
             const int* __restrict__ iw_p,
             float* __restrict__ out) {
    __shared__ SmemAll sm;
    const int tid  = threadIdx.x;
    const int bid  = blockIdx.x;
    const int lane = tid & 31;
    const int wid  = tid >> 5;

    // ====== Phase A: lse + transposed softmax probs (warp per proposal) ======
    if (bid == 0 && tid == 0) g_count = 0;
    {
        const int gw = bid * (NTHREADS / 32) + wid;     // 0..639
        #pragma unroll
        for (int pass = 0; pass < 2; pass++) {
            int p = gw + pass * (NBLOCKS * NTHREADS / 32);
            if (p < N_PROP) {
                const float* row = logits + p * NUM_CLASSES;
                float v0 = row[lane];
                float v1 = row[lane + 32];
                bool has2 = (lane + 64 < NUM_CLASSES);
                float v2 = has2 ? row[lane + 64] : -INFINITY;
                float m = fmaxf(fmaxf(v0, v1), v2);
                #pragma unroll
                for (int o = 16; o > 0; o >>= 1) m = fmaxf(m, __shfl_xor_sync(0xffffffffu, m, o));
                float s = expf(v0 - m) + expf(v1 - m);
                if (has2) s += expf(v2 - m);
                #pragma unroll
                for (int o = 16; o > 0; o >>= 1) s += __shfl_xor_sync(0xffffffffu, s, o);
                float lse = m + logf(s);                 // same on all lanes
                g_probT[lane * PROB_PITCH + p]        = expf(v0 - lse);
                g_probT[(lane + 32) * PROB_PITCH + p] = expf(v1 - lse);
                if (has2)
                    g_probT[(lane + 64) * PROB_PITCH + p] = expf(v2 - lse);
            }
        }
    }
    grid_sync();

    // ================= Phase B: per-class decode + sort + NMS =================
    {
        const int c = bid + 1;               // foreground class 1..80
        if (tid == 0) sm.nms.cnt = 0;
        __syncthreads();

        const float W = load_dim(iw_p) - 1.0f;
        const float H = load_dim(ih_p) - 1.0f;
        const float* prow = g_probT + c * PROB_PITCH;
        const float4* pb4 = (const float4*)pboxes;
        const float4* dl4 = (const float4*)deltas;   // [1000][81] float4 blocks

        for (int p = tid; p < N_PROP; p += NTHREADS) {
            float sc = prow[p];                        // coalesced
            if (sc > SCORE_THRESH) {
                float4 pb = pb4[p];
                float w  = pb.z - pb.x + 1.0f,  h  = pb.w - pb.y + 1.0f;
                float cx = pb.x + 0.5f * w,     cy = pb.y + 0.5f * h;
                float4 d = dl4[p * NUM_CLASSES + c];
                float dx = d.x / 10.0f;
                float dy = d.y / 10.0f;
                float dw = fminf(d.z / 5.0f, BBOX_XFORM_CLIP);
                float dh = fminf(d.w / 5.0f, BBOX_XFORM_CLIP);
                float pcx = dx * w + cx, pcy = dy * h + cy;
                float pw  = expf(dw) * w, ph = expf(dh) * h;
                float bx1 = fminf(fmaxf(pcx - 0.5f * pw, 0.0f), W);
                float by1 = fminf(fmaxf(pcy - 0.5f * ph, 0.0f), H);
                float bx2 = fminf(fmaxf(pcx + 0.5f * pw - 1.0f, 0.0f), W);
                float by2 = fminf(fmaxf(pcy + 0.5f * ph - 1.0f, 0.0f), H);
                int slot = atomicAdd(&sm.nms.cnt, 1);
                sm.nms.key[slot] = ((u64)__float_as_uint(sc) << 32) | (u32)(~p);
                sm.nms.box[slot] = make_float4(bx1, by1, bx2, by2);
            }
        }
        __syncthreads();
        const int M = sm.nms.cnt;

        if (M > 0) {
            // bitonic sort descending on packed u64 (ties -> smaller p first)
            int P = 1;
            while (P < M) P <<= 1;
            for (int i = M + tid; i < P; i += NTHREADS) sm.nms.key[i] = 0ULL;
            __syncthreads();

            for (int k = 2; k <= P; k <<= 1) {
                for (int j = k >> 1; j > 0; j >>= 1) {
                    for (int i = tid; i < P; i += NTHREADS) {
                        int ixj = i ^ j;
                        if (ixj > i) {
                            u64 a = sm.nms.key[i], b = sm.nms.key[ixj];
                            bool up = ((i & k) == 0);
                            if (up ? (a < b) : (a > b)) {
                                sm.nms.key[i] = b; sm.nms.key[ixj] = a;
                                float4 tb = sm.nms.box[i];
                                sm.nms.box[i] = sm.nms.box[ixj];
                                sm.nms.box[ixj] = tb;
                            }
                        }
                    }
                    __syncthreads();
                }
            }

            const bool shpath = (M <= MROW_SH);
            const int mwords = shpath ? MWORDS_SH : MWORDS;
            u32* mask = shpath ? sm.nms.masksh : &g_mask[bid * MROW * MWORDS];
            const int Wd = (M + 31) >> 5;

            // build suppression rows (row i: bits j>i with IoU>thresh)
            for (int i = tid; i < M; i += NTHREADS) {
                u32* row = &mask[i * mwords];
                for (int w = 0; w < Wd; w++) row[w] = 0;
                float4 bi = sm.nms.box[i];
                float ai = (bi.z - bi.x + 1.0f) * (bi.w - bi.y + 1.0f);
                u32 cur = 0; int curw = (i + 1) >> 5;
                for (int j = i + 1; j < M; j++) {
                    int w = j >> 5;
                    if (w != curw) {
                        if (cur) row[curw] = cur;
                        cur = 0; curw = w;
                    }
                    float4 bj = sm.nms.box[j];
                    float lx = fmaxf(bi.x, bj.x), ly = fmaxf(bi.y, bj.y);
                    float rx = fminf(bi.z, bj.z), ry = fminf(bi.w, bj.w);
                    float iw = fmaxf(rx - lx + 1.0f, 0.0f);
                    float ih = fmaxf(ry - ly + 1.0f, 0.0f);
                    float inter = iw * ih;
                    float aj = (bj.z - bj.x + 1.0f) * (bj.w - bj.y + 1.0f);
                    if (inter / (ai + aj - inter) > NMS_THRESH) cur |= 1u << (j & 31);
                }
                if (cur) row[curw] = cur;
            }
            __syncthreads();

            // greedy resolve: warp 0, lane = mask word
            if (tid < 32) {
                u32 kw = (lane < Wd) ? 0xffffffffu : 0u;
                int rem = M & 31;
                if (rem && lane == Wd - 1) kw = (1u << rem) - 1u;
                for (int i = 0; i < M; i++) {
                    u32 srcw = __shfl_sync(0xffffffffu, kw, i >> 5);
                    if ((srcw >> (i & 31)) & 1u) {
                        u32 rw = (lane < Wd) ? mask[i * mwords + lane] : 0u;
                        kw &= ~rw;
                    }
                }
                if (lane < Wd) sm.nms.keepw[lane] = kw;
            }
            __syncthreads();

            // block-scan append: one global atomic per class
            if (tid == 0) {
                int run = 0;
                for (int w = 0; w < Wd; w++) {
                    sm.nms.wpfx[w] = run;
                    run += __popc(sm.nms.keepw[w]);
                }
                sm.nms.wpfx[Wd] = run;
                sm.nms.base = atomicAdd(&g_count, run);
            }
            __syncthreads();
            const int base = sm.nms.base;

            for (int j = tid; j < M; j += NTHREADS) {
                u32 kwj = sm.nms.keepw[j >> 5];
                if ((kwj >> (j & 31)) & 1u) {
                    int rank = sm.nms.wpfx[j >> 5] + __popc(kwj & ((1u << (j & 31)) - 1u));
                    int pos = base + rank;
                    int key = bid * N_PROP + j;      // reference flat index
                    g_cscore[pos] = __uint_as_float((u32)(sm.nms.key[j] >> 32));
                    g_ckey[pos]   = key;
                    g_boxkey[key] = sm.nms.box[j];
                }
            }
        }
    }
    grid_sync();

    // ================= Phase C: block 0 top-100 =================
    if (bid != 0) return;

    const int K = g_count;
    const int target = (K < DET_PER_IMG) ? K : DET_PER_IMG;

    for (int i = tid; i < NBINS; i += NTHREADS) sm.topk.hist[i] = 0;
    if (tid == 0) { sm.topk.bstar = 0; sm.topk.cnt = 0; }
    __syncthreads();

    for (int i = tid; i < K; i += NTHREADS)
        atomicAdd(&sm.topk.hist[score_bin(__float_as_uint(g_cscore[i]))], 1);
    __syncthreads();

    // suffix scan over 256 chunks of 16 bins
    const int CH = NBINS / NTHREADS;        // 16
    const int base = tid * CH;
    int cs[16];
    int sum = 0;
    #pragma unroll
    for (int t = 0; t < CH; t++) { cs[t] = sm.topk.hist[base + t]; sum += cs[t]; }
    sm.topk.part[tid] = sum;
    __syncthreads();
    for (int off = 1; off < NTHREADS; off <<= 1) {
        int add = (tid + off < NTHREADS) ? sm.topk.part[tid + off] : 0;
        __syncthreads();
        sm.topk.part[tid] += add;
        __syncthreads();
    }
    {
        int suf = (tid < NTHREADS - 1) ? sm.topk.part[tid + 1] : 0;
        #pragma unroll
        for (int t = CH - 1; t >= 0; t--) {
            suf += cs[t];
            if (suf >= target) { atomicMax(&sm.topk.bstar, base + t); break; }
        }
    }
    __syncthreads();
    const int bstar = sm.topk.bstar;

    for (int i = tid; i < K; i += NTHREADS) {
        u32 sb = __float_as_uint(g_cscore[i]);
        if (score_bin(sb) >= bstar) {
            int pos = atomicAdd(&sm.topk.cnt, 1);
            if (pos < TOPK_CAP)
                sm.topk.buf[pos] = ((u64)sb << 32) | (u32)(~g_ckey[i]);
        }
    }
    __syncthreads();
    const int C = sm.topk.cnt;

    if (C <= TOPK_CAP) {
        int P2 = 128;
        while (P2 < C) P2 <<= 1;
        for (int i = C + tid; i < P2; i += NTHREADS) sm.topk.buf[i] = 0ULL;
        __syncthreads();

        for (int k = 2; k <= P2; k <<= 1) {
            for (int j = k >> 1; j > 0; j >>= 1) {
                for (int i = tid; i < P2; i += NTHREADS) {
                    int ixj = i ^ j;
                    if (ixj > i) {
                        u64 a = sm.topk.buf[i], b = sm.topk.buf[ixj];
                        bool up = ((i & k) == 0);
                        if (up ? (a < b) : (a > b)) { sm.topk.buf[i] = b; sm.topk.buf[ixj] = a; }
                    }
                }
                __syncthreads();
            }
        }

        for (int r = tid; r < DET_PER_IMG; r += NTHREADS) {
            if (r < C) {
                u64 v = sm.topk.buf[r];
                int key = (int)(~(u32)v);
                float4 b = g_boxkey[key];
                out[r] = __uint_as_float((u32)(v >> 32));
                out[DET_PER_IMG + r * 4 + 0] = b.x;
                out[DET_PER_IMG + r * 4 + 1] = b.y;
                out[DET_PER_IMG + r * 4 + 2] = b.z;
                out[DET_PER_IMG + r * 4 + 3] = b.w;
                out[DET_PER_IMG * 5 + r] = (float)(key / N_PROP + 1);
            } else {
                out[r] = 0.0f;
                out[DET_PER_IMG + r * 4 + 0] = 0.0f;
                out[DET_PER_IMG + r * 4 + 1] = 0.0f;
                out[DET_PER_IMG + r * 4 + 2] = 0.0f;
                out[DET_PER_IMG + r * 4 + 3] = 0.0f;
                out[DET_PER_IMG * 5 + r] = 0.0f;
            }
        }
        return;
    }

    // -------- fallback: repeated global argmax (C > TOPK_CAP, pathological) ------
    u64* r_v = sm.topk.buf;                 // alias
    int* r_i = (int*)(sm.topk.buf + NTHREADS);
    __syncthreads();
    for (int r = 0; r < DET_PER_IMG; r++) {
        u64 bv = 0ULL; int bi = -1;
        for (int i = tid; i < K; i += NTHREADS) {
            u32 sb = __float_as_uint(g_cscore[i]);
            u64 v = ((u64)sb << 32) | (u32)(~g_ckey[i]);
            if (v > bv) { bv = v; bi = i; }
        }
        r_v[tid] = bv; r_i[tid] = bi;
        __syncthreads();
        for (int off = NTHREADS >> 1; off > 0; off >>= 1) {
            if (tid < off) {
                if (r_v[tid + off] > r_v[tid]) { r_v[tid] = r_v[tid + off]; r_i[tid] = r_i[tid + off]; }
            }
            __syncthreads();
        }
        if (tid == 0) {
            int idx = r_i[0];
            u64 v = r_v[0];
            int key = (int)(~(u32)v);
            float4 b = g_boxkey[key];
            out[r] = __uint_as_float((u32)(v >> 32));
            out[DET_PER_IMG + r * 4 + 0] = b.x;
            out[DET_PER_IMG + r * 4 + 1] = b.y;
            out[DET_PER_IMG + r * 4 + 2] = b.z;
            out[DET_PER_IMG + r * 4 + 3] = b.w;
            out[DET_PER_IMG * 5 + r] = (float)(key / N_PROP + 1);
            g_cscore[idx] = 0.0f;
        }
        __syncthreads();
    }
}

extern "C" void kernel_launch(void* const* d_in, const int* in_sizes, int n_in,
                              void* d_out, int out_size) {
    const float* logits = (const float*)d_in[0];   // [1000, 81]
    const float* deltas = (const float*)d_in[1];   // [1000, 324]
    const float* pboxes = (const float*)d_in[2];   // [1000, 4]
    const int*   ih     = (const int*)d_in[3];     // scalar
    const int*   iw     = (const int*)d_in[4];     // scalar

    fused_kernel<<<NBLOCKS, NTHREADS>>>(logits, deltas, pboxes, ih, iw, (float*)d_out);
}

// round 10
// speedup vs baseline: 1.0075x; 1.0075x over previous
#include <cuda_runtime.h>
#include <math.h>

#define N_PROP 1000
#define NUM_CLASSES 81
#define NUM_FG 80
#define SCORE_THRESH 0.05f
#define NMS_THRESH 0.5f
#define DET_PER_IMG 100
#define BBOX_XFORM_CLIP 4.135166556742356f
#define CAND_MAX (N_PROP * NUM_FG)

#define NBLOCKS 80
#define NTHREADS 1024

#define PROB_PITCH 1024      // padded row pitch for transposed probs

#define MROW 1024            // global-mask rows (fallback, M <= 1000)
#define MWORDS 32            // 1024 bits
#define MROW_SH 256          // shared-mask rows (fast path)
#define MWORDS_SH 8          // 256 bits

#define NBINS 4096
#define TOPK_CAP 2048

typedef unsigned long long u64;
typedef unsigned int u32;

// ---------- device scratch (no allocations allowed) ----------
__device__ float  g_probT[NUM_CLASSES * PROB_PITCH];   // [class][proposal]
__device__ int    g_count;
__device__ float  g_cscore[CAND_MAX];
__device__ int    g_ckey[CAND_MAX];
__device__ float4 g_boxkey[CAND_MAX];
__device__ u32    g_mask[NUM_FG * MROW * MWORDS];      // fallback mask (M > 256)

// self-resetting grid barrier state (gen is monotonic across graph replays)
__device__ unsigned int g_bar_count = 0;
__device__ unsigned int g_bar_gen   = 0;

__device__ __forceinline__ void grid_sync() {
    __threadfence();
    __syncthreads();
    if (threadIdx.x == 0) {
        unsigned gen = *((volatile unsigned*)&g_bar_gen);
        unsigned old = atomicInc(&g_bar_count, NBLOCKS - 1);   // wraps to 0 -> self-reset
        if (old == NBLOCKS - 1) {
            atomicAdd(&g_bar_gen, 1);
        } else {
            while (*((volatile unsigned*)&g_bar_gen) == gen) {}
        }
    }
    __syncthreads();
    __threadfence();
}

__device__ __forceinline__ float load_dim(const int* p) {
    int vi = *p;
    if (vi > 0 && vi < 100000) return (float)vi;
    return __int_as_float(vi);
}

__device__ __forceinline__ int score_bin(u32 bits) {
    int b = (int)(bits >> 14) - 0xF400;      // scores in (0.05, 1] -> positive bins
    return min(NBINS - 1, max(0, b));
}

// ---------- shared memory union across phases ----------
struct SmemNMS {
    u64    key[1024];        // (score_bits<<32) | ~prop_idx
    float4 box[1024];
    u32    masksh[MROW_SH * MWORDS_SH];
    u32    keepw[MWORDS];
    int    wpfx[MWORDS + 1]; // popcount prefix of keepw
    int    base;
    int    cnt;
};
struct SmemTopk {
    u64 buf[TOPK_CAP];
    int hist[NBINS];
    int part[NTHREADS];
    int bstar;
    int cnt;
};
union SmemAll {
    SmemNMS  nms;
    SmemTopk topk;
};

__global__ void __launch_bounds__(NTHREADS, 1)
fused_kernel(const float* __restrict__ logits,
             const float* __restrict__ deltas,
             const float* __restrict__ pboxes,
             const int* __restrict__ ih_p,
             const int* __restrict__ iw_p,
             float* __restrict__ out) {
    __shared__ SmemAll sm;
    const int tid  = threadIdx.x;
    const int bid  = blockIdx.x;
    const int lane = tid & 31;
    const int wid  = tid >> 5;

    // ====== Phase A: lse + transposed softmax probs (warp per proposal) ======
    if (bid == 0 && tid == 0) g_count = 0;
    {
        const int p = bid * (NTHREADS / 32) + wid;      // 0..2559 >= N_PROP: 1 pass
        if (p < N_PROP) {
            const float* row = logits + p * NUM_CLASSES;
            float v0 = row[lane];
            float v1 = row[lane + 32];
            bool has2 = (lane + 64 < NUM_CLASSES);
            float v2 = has2 ? row[lane + 64] : -INFINITY;
            float m = fmaxf(fmaxf(v0, v1), v2);
            #pragma unroll
            for (int o = 16; o > 0; o >>= 1) m = fmaxf(m, __shfl_xor_sync(0xffffffffu, m, o));
            float s = expf(v0 - m) + expf(v1 - m);
            if (has2) s += expf(v2 - m);
            #pragma unroll
            for (int o = 16; o > 0; o >>= 1) s += __shfl_xor_sync(0xffffffffu, s, o);
            float lse = m + logf(s);                    // same on all lanes
            g_probT[lane * PROB_PITCH + p]        = expf(v0 - lse);
            g_probT[(lane + 32) * PROB_PITCH + p] = expf(v1 - lse);
            if (has2)
                g_probT[(lane + 64) * PROB_PITCH + p] = expf(v2 - lse);
        }
    }
    grid_sync();

    // ================= Phase B: per-class decode + sort + NMS =================
    {
        const int c = bid + 1;               // foreground class 1..80
        if (tid == 0) sm.nms.cnt = 0;
        __syncthreads();

        const float W = load_dim(iw_p) - 1.0f;
        const float H = load_dim(ih_p) - 1.0f;
        const float* prow = g_probT + c * PROB_PITCH;
        const float4* pb4 = (const float4*)pboxes;
        const float4* dl4 = (const float4*)deltas;   // [1000][81] float4 blocks

        for (int p = tid; p < N_PROP; p += NTHREADS) {
            float sc = prow[p];                        // coalesced
            if (sc > SCORE_THRESH) {
                float4 pb = pb4[p];
                float w  = pb.z - pb.x + 1.0f,  h  = pb.w - pb.y + 1.0f;
                float cx = pb.x + 0.5f * w,     cy = pb.y + 0.5f * h;
                float4 d = dl4[p * NUM_CLASSES + c];
                float dx = d.x / 10.0f;
                float dy = d.y / 10.0f;
                float dw = fminf(d.z / 5.0f, BBOX_XFORM_CLIP);
                float dh = fminf(d.w / 5.0f, BBOX_XFORM_CLIP);
                float pcx = dx * w + cx, pcy = dy * h + cy;
                float pw  = expf(dw) * w, ph = expf(dh) * h;
                float bx1 = fminf(fmaxf(pcx - 0.5f * pw, 0.0f), W);
                float by1 = fminf(fmaxf(pcy - 0.5f * ph, 0.0f), H);
                float bx2 = fminf(fmaxf(pcx + 0.5f * pw - 1.0f, 0.0f), W);
                float by2 = fminf(fmaxf(pcy + 0.5f * ph - 1.0f, 0.0f), H);
                int slot = atomicAdd(&sm.nms.cnt, 1);
                sm.nms.key[slot] = ((u64)__float_as_uint(sc) << 32) | (u32)(~p);
                sm.nms.box[slot] = make_float4(bx1, by1, bx2, by2);
            }
        }
        __syncthreads();
        const int M = sm.nms.cnt;

        if (M > 0) {
            // bitonic sort descending on packed u64 (ties -> smaller p first)
            int P = 1;
            while (P < M) P <<= 1;
            for (int i = M + tid; i < P; i += NTHREADS) sm.nms.key[i] = 0ULL;
            __syncthreads();

            for (int k = 2; k <= P; k <<= 1) {
                for (int j = k >> 1; j > 0; j >>= 1) {
                    for (int i = tid; i < P; i += NTHREADS) {
                        int ixj = i ^ j;
                        if (ixj > i) {
                            u64 a = sm.nms.key[i], b = sm.nms.key[ixj];
                            bool up = ((i & k) == 0);
                            if (up ? (a < b) : (a > b)) {
                                sm.nms.key[i] = b; sm.nms.key[ixj] = a;
                                float4 tb = sm.nms.box[i];
                                sm.nms.box[i] = sm.nms.box[ixj];
                                sm.nms.box[ixj] = tb;
                            }
                        }
                    }
                    __syncthreads();
                }
            }

            const bool shpath = (M <= MROW_SH);
            const int mwords = shpath ? MWORDS_SH : MWORDS;
            u32* mask = shpath ? sm.nms.masksh : &g_mask[bid * MROW * MWORDS];
            const int Wd = (M + 31) >> 5;

            // build suppression rows (row i: bits j>i with IoU>thresh) — 1 row/thread
            for (int i = tid; i < M; i += NTHREADS) {
                u32* row = &mask[i * mwords];
                for (int w = 0; w < Wd; w++) row[w] = 0;
                float4 bi = sm.nms.box[i];
                float ai = (bi.z - bi.x + 1.0f) * (bi.w - bi.y + 1.0f);
                u32 cur = 0; int curw = (i + 1) >> 5;
                for (int j = i + 1; j < M; j++) {
                    int w = j >> 5;
                    if (w != curw) {
                        if (cur) row[curw] = cur;
                        cur = 0; curw = w;
                    }
                    float4 bj = sm.nms.box[j];
                    float lx = fmaxf(bi.x, bj.x), ly = fmaxf(bi.y, bj.y);
                    float rx = fminf(bi.z, bj.z), ry = fminf(bi.w, bj.w);
                    float iw = fmaxf(rx - lx + 1.0f, 0.0f);
                    float ih = fmaxf(ry - ly + 1.0f, 0.0f);
                    float inter = iw * ih;
                    float aj = (bj.z - bj.x + 1.0f) * (bj.w - bj.y + 1.0f);
                    if (inter / (ai + aj - inter) > NMS_THRESH) cur |= 1u << (j & 31);
                }
                if (cur) row[curw] = cur;
            }
            __syncthreads();

            // greedy resolve: warp 0, lane = mask word
            if (tid < 32) {
                u32 kw = (lane < Wd) ? 0xffffffffu : 0u;
                int rem = M & 31;
                if (rem && lane == Wd - 1) kw = (1u << rem) - 1u;
                for (int i = 0; i < M; i++) {
                    u32 srcw = __shfl_sync(0xffffffffu, kw, i >> 5);
                    if ((srcw >> (i & 31)) & 1u) {
                        u32 rw = (lane < Wd) ? mask[i * mwords + lane] : 0u;
                        kw &= ~rw;
                    }
                }
                if (lane < Wd) sm.nms.keepw[lane] = kw;
            }
            __syncthreads();

            // block-scan append: one global atomic per class
            if (tid == 0) {
                int run = 0;
                for (int w = 0; w < Wd; w++) {
                    sm.nms.wpfx[w] = run;
                    run += __popc(sm.nms.keepw[w]);
                }
                sm.nms.wpfx[Wd] = run;
                sm.nms.base = atomicAdd(&g_count, run);
            }
            __syncthreads();
            const int base = sm.nms.base;

            for (int j = tid; j < M; j += NTHREADS) {
                u32 kwj = sm.nms.keepw[j >> 5];
                if ((kwj >> (j & 31)) & 1u) {
                    int rank = sm.nms.wpfx[j >> 5] + __popc(kwj & ((1u << (j & 31)) - 1u));
                    int pos = base + rank;
                    int key = bid * N_PROP + j;      // reference flat index
                    g_cscore[pos] = __uint_as_float((u32)(sm.nms.key[j] >> 32));
                    g_ckey[pos]   = key;
                    g_boxkey[key] = sm.nms.box[j];
                }
            }
        }
    }
    grid_sync();

    // ================= Phase C: block 0 top-100 =================
    if (bid != 0) return;

    const int K = g_count;
    const int target = (K < DET_PER_IMG) ? K : DET_PER_IMG;

    for (int i = tid; i < NBINS; i += NTHREADS) sm.topk.hist[i] = 0;
    if (tid == 0) { sm.topk.bstar = 0; sm.topk.cnt = 0; }
    __syncthreads();

    for (int i = tid; i < K; i += NTHREADS)
        atomicAdd(&sm.topk.hist[score_bin(__float_as_uint(g_cscore[i]))], 1);
    __syncthreads();

    // suffix scan over NTHREADS chunks of CH bins
    const int CH = NBINS / NTHREADS;        // 4
    const int base = tid * CH;
    int cs[CH];
    int sum = 0;
    #pragma unroll
    for (int t = 0; t < CH; t++) { cs[t] = sm.topk.hist[base + t]; sum += cs[t]; }
    sm.topk.part[tid] = sum;
    __syncthreads();
    for (int off = 1; off < NTHREADS; off <<= 1) {
        int add = (tid + off < NTHREADS) ? sm.topk.part[tid + off] : 0;
        __syncthreads();
        sm.topk.part[tid] += add;
        __syncthreads();
    }
    {
        int suf = (tid < NTHREADS - 1) ? sm.topk.part[tid + 1] : 0;
        #pragma unroll
        for (int t = CH - 1; t >= 0; t--) {
            suf += cs[t];
            if (suf >= target) { atomicMax(&sm.topk.bstar, base + t); break; }
        }
    }
    __syncthreads();
    const int bstar = sm.topk.bstar;

    for (int i = tid; i < K; i += NTHREADS) {
        u32 sb = __float_as_uint(g_cscore[i]);
        if (score_bin(sb) >= bstar) {
            int pos = atomicAdd(&sm.topk.cnt, 1);
            if (pos < TOPK_CAP)
                sm.topk.buf[pos] = ((u64)sb << 32) | (u32)(~g_ckey[i]);
        }
    }
    __syncthreads();
    const int C = sm.topk.cnt;

    if (C <= TOPK_CAP) {
        int P2 = 128;
        while (P2 < C) P2 <<= 1;
        for (int i = C + tid; i < P2; i += NTHREADS) sm.topk.buf[i] = 0ULL;
        __syncthreads();

        for (int k = 2; k <= P2; k <<= 1) {
            for (int j = k >> 1; j > 0; j >>= 1) {
                for (int i = tid; i < P2; i += NTHREADS) {
                    int ixj = i ^ j;
                    if (ixj > i) {
                        u64 a = sm.topk.buf[i], b = sm.topk.buf[ixj];
                        bool up = ((i & k) == 0);
                        if (up ? (a < b) : (a > b)) { sm.topk.buf[i] = b; sm.topk.buf[ixj] = a; }
                    }
                }
                __syncthreads();
            }
        }

        for (int r = tid; r < DET_PER_IMG; r += NTHREADS) {
            if (r < C) {
                u64 v = sm.topk.buf[r];
                int key = (int)(~(u32)v);
                float4 b = g_boxkey[key];
                out[r] = __uint_as_float((u32)(v >> 32));
                out[DET_PER_IMG + r * 4 + 0] = b.x;
                out[DET_PER_IMG + r * 4 + 1] = b.y;
                out[DET_PER_IMG + r * 4 + 2] = b.z;
                out[DET_PER_IMG + r * 4 + 3] = b.w;
                out[DET_PER_IMG * 5 + r] = (float)(key / N_PROP + 1);
            } else {
                out[r] = 0.0f;
                out[DET_PER_IMG + r * 4 + 0] = 0.0f;
                out[DET_PER_IMG + r * 4 + 1] = 0.0f;
                out[DET_PER_IMG + r * 4 + 2] = 0.0f;
                out[DET_PER_IMG + r * 4 + 3] = 0.0f;
                out[DET_PER_IMG * 5 + r] = 0.0f;
            }
        }
        return;
    }

    // -------- fallback: repeated global argmax (C > TOPK_CAP, pathological) ------
    u64* r_v = sm.topk.buf;                 // alias (NTHREADS u64 + NTHREADS int <= CAP u64)
    int* r_i = (int*)(sm.topk.buf + NTHREADS);
    __syncthreads();
    for (int r = 0; r < DET_PER_IMG; r++) {
        u64 bv = 0ULL; int bi = -1;
        for (int i = tid; i < K; i += NTHREADS) {
            u32 sb = __float_as_uint(g_cscore[i]);
            u64 v = ((u64)sb << 32) | (u32)(~g_ckey[i]);
            if (v > bv) { bv = v; bi = i; }
        }
        r_v[tid] = bv; r_i[tid] = bi;
        __syncthreads();
        for (int off = NTHREADS >> 1; off > 0; off >>= 1) {
            if (tid < off) {
                if (r_v[tid + off] > r_v[tid]) { r_v[tid] = r_v[tid + off]; r_i[tid] = r_i[tid + off]; }
            }
            __syncthreads();
        }
        if (tid == 0) {
            int idx = r_i[0];
            u64 v = r_v[0];
            int key = (int)(~(u32)v);
            float4 b = g_boxkey[key];
            out[r] = __uint_as_float((u32)(v >> 32));
            out[DET_PER_IMG + r * 4 + 0] = b.x;
            out[DET_PER_IMG + r * 4 + 1] = b.y;
            out[DET_PER_IMG + r * 4 + 2] = b.z;
            out[DET_PER_IMG + r * 4 + 3] = b.w;
            out[DET_PER_IMG * 5 + r] = (float)(key / N_PROP + 1);
            g_cscore[idx] = 0.0f;
        }
        __syncthreads();
    }
}

extern "C" void kernel_launch(void* const* d_in, const int* in_sizes, int n_in,
                              void* d_out, int out_size) {
    const float* logits = (const float*)d_in[0];   // [1000, 81]
    const float* deltas = (const float*)d_in[1];   // [1000, 324]
    const float* pboxes = (const float*)d_in[2];   // [1000, 4]
    const int*   ih     = (const int*)d_in[3];     // scalar
    const int*   iw     = (const int*)d_in[4];     // scalar

    fused_kernel<<<NBLOCKS, NTHREADS>>>(logits, deltas, pboxes, ih, iw, (float*)d_out);
}

// round 11
// speedup vs baseline: 1.3993x; 1.3889x over previous
#include <cuda_runtime.h>
#include <math.h>

#define N_PROP 1000
#define NUM_CLASSES 81
#define NUM_FG 80
#define SCORE_THRESH 0.05f
#define NMS_THRESH 0.5f
#define DET_PER_IMG 100
#define BBOX_XFORM_CLIP 4.135166556742356f
#define CAND_MAX (N_PROP * NUM_FG)

#define NBLOCKS 80
#define NTHREADS 1024

#define PROB_PITCH 1024      // padded row pitch for transposed probs

#define MROW 1024            // global-mask rows (fallback, M > 256)
#define MWORDS 32            // 1024 bits
#define MROW_SH 256          // shared-mask rows (fast path)
#define MWORDS_SH 8          // 256 bits

#define NBINS 4096
#define TOPK_CAP 2048

typedef unsigned long long u64;
typedef unsigned int u32;

// ---------- device scratch (no allocations allowed) ----------
__device__ float  g_probT[NUM_CLASSES * PROB_PITCH];   // [class][proposal]
__device__ int    g_count;
__device__ int    g_hist[NBINS];                       // global histogram (built in Phase B)
__device__ float  g_cscore[CAND_MAX];
__device__ int    g_ckey[CAND_MAX];
__device__ float4 g_boxkey[CAND_MAX];
__device__ u32    g_mask[NUM_FG * MROW * MWORDS];      // fallback mask (M > 256)

// self-resetting grid barrier state (gen is monotonic across graph replays)
__device__ unsigned int g_bar_count = 0;
__device__ unsigned int g_bar_gen   = 0;

__device__ __forceinline__ void grid_sync() {
    __threadfence();
    __syncthreads();
    if (threadIdx.x == 0) {
        unsigned gen = *((volatile unsigned*)&g_bar_gen);
        unsigned old = atomicInc(&g_bar_count, NBLOCKS - 1);   // wraps to 0 -> self-reset
        if (old == NBLOCKS - 1) {
            atomicAdd(&g_bar_gen, 1);
        } else {
            while (*((volatile unsigned*)&g_bar_gen) == gen) {}
        }
    }
    __syncthreads();
    __threadfence();
}

__device__ __forceinline__ float load_dim(const int* p) {
    int vi = *p;
    if (vi > 0 && vi < 100000) return (float)vi;
    return __int_as_float(vi);
}

__device__ __forceinline__ int score_bin(u32 bits) {
    int b = (int)(bits >> 14) - 0xF400;      // scores in (0.05, 1] -> positive bins
    return min(NBINS - 1, max(0, b));
}

// ---------- shared memory union across phases ----------
struct SmemNMS {
    u64    key[1024];        // (score_bits<<32) | ~prop_idx
    float4 boxp[1024];       // box indexed by PROPOSAL id (no sort payload)
    u32    masksh[MROW_SH * MWORDS_SH];
    u32    keepw[MWORDS];
    int    wpfx[MWORDS + 1];
    int    base;
    int    cnt;
};
struct SmemTopk {
    u64 buf[TOPK_CAP];
    int part[NTHREADS];
    int bstar;
    int cnt;
};
union SmemAll {
    SmemNMS  nms;
    SmemTopk topk;
};

__global__ void __launch_bounds__(NTHREADS, 1)
fused_kernel(const float* __restrict__ logits,
             const float* __restrict__ deltas,
             const float* __restrict__ pboxes,
             const int* __restrict__ ih_p,
             const int* __restrict__ iw_p,
             float* __restrict__ out) {
    __shared__ SmemAll sm;
    const int tid  = threadIdx.x;
    const int bid  = blockIdx.x;
    const int lane = tid & 31;
    const int wid  = tid >> 5;

    // ====== Phase A: lse + transposed softmax probs (warp per proposal) ======
    if (bid == 0 && tid == 0) g_count = 0;
    {
        int z = bid * NTHREADS + tid;
        if (z < NBINS) g_hist[z] = 0;
    }
    {
        const int p = bid * (NTHREADS / 32) + wid;      // 0..2559: single pass
        if (p < N_PROP) {
            const float* row = logits + p * NUM_CLASSES;
            float v0 = row[lane];
            float v1 = row[lane + 32];
            bool has2 = (lane + 64 < NUM_CLASSES);
            float v2 = has2 ? row[lane + 64] : -INFINITY;
            float m = fmaxf(fmaxf(v0, v1), v2);
            #pragma unroll
            for (int o = 16; o > 0; o >>= 1) m = fmaxf(m, __shfl_xor_sync(0xffffffffu, m, o));
            float s = expf(v0 - m) + expf(v1 - m);
            if (has2) s += expf(v2 - m);
            #pragma unroll
            for (int o = 16; o > 0; o >>= 1) s += __shfl_xor_sync(0xffffffffu, s, o);
            float lse = m + logf(s);                    // same on all lanes
            g_probT[lane * PROB_PITCH + p]        = expf(v0 - lse);
            g_probT[(lane + 32) * PROB_PITCH + p] = expf(v1 - lse);
            if (has2)
                g_probT[(lane + 64) * PROB_PITCH + p] = expf(v2 - lse);
        }
    }
    grid_sync();

    // ================= Phase B: per-class decode + sort + NMS =================
    {
        const int c = bid + 1;               // foreground class 1..80
        if (tid == 0) sm.nms.cnt = 0;
        __syncthreads();

        const float W = load_dim(iw_p) - 1.0f;
        const float H = load_dim(ih_p) - 1.0f;
        const float* prow = g_probT + c * PROB_PITCH;
        const float4* pb4 = (const float4*)pboxes;
        const float4* dl4 = (const float4*)deltas;

        for (int p = tid; p < N_PROP; p += NTHREADS) {
            float sc = prow[p];
            if (sc > SCORE_THRESH) {
                float4 pb = pb4[p];
                float w  = pb.z - pb.x + 1.0f,  h  = pb.w - pb.y + 1.0f;
                float cx = pb.x + 0.5f * w,     cy = pb.y + 0.5f * h;
                float4 d = dl4[p * NUM_CLASSES + c];
                float dx = d.x / 10.0f;
                float dy = d.y / 10.0f;
                float dw = fminf(d.z / 5.0f, BBOX_XFORM_CLIP);
                float dh = fminf(d.w / 5.0f, BBOX_XFORM_CLIP);
                float pcx = dx * w + cx, pcy = dy * h + cy;
                float pw  = expf(dw) * w, ph = expf(dh) * h;
                float bx1 = fminf(fmaxf(pcx - 0.5f * pw, 0.0f), W);
                float by1 = fminf(fmaxf(pcy - 0.5f * ph, 0.0f), H);
                float bx2 = fminf(fmaxf(pcx + 0.5f * pw - 1.0f, 0.0f), W);
                float by2 = fminf(fmaxf(pcy + 0.5f * ph - 1.0f, 0.0f), H);
                int slot = atomicAdd(&sm.nms.cnt, 1);
                sm.nms.key[slot] = ((u64)__float_as_uint(sc) << 32) | (u32)(~p);
                sm.nms.boxp[p]   = make_float4(bx1, by1, bx2, by2);
            }
        }
        __syncthreads();
        const int M = sm.nms.cnt;

        if (M > 0) {
            // ---- keys-only hybrid bitonic sort, register-resident (P <= 1024) ----
            int P = 32;
            while (P < M) P <<= 1;
            u64 v = (tid < M) ? sm.nms.key[tid] : 0ULL;
            for (int k = 2; k <= P; k <<= 1) {
                for (int j = k >> 1; j > 0; j >>= 1) {
                    if (j >= 32) {
                        __syncthreads();
                        if (tid < P) sm.nms.key[tid] = v;
                        __syncthreads();
                        if (tid < P) {
                            u64 o = sm.nms.key[tid ^ j];
                            bool takeMax = ((tid & k) == 0) == ((tid & j) == 0);
                            v = takeMax ? (v > o ? v : o) : (v < o ? v : o);
                        }
                    } else {
                        u64 o = __shfl_xor_sync(0xffffffffu, v, j);
                        bool takeMax = ((tid & k) == 0) == ((tid & j) == 0);
                        v = takeMax ? (v > o ? v : o) : (v < o ? v : o);
                    }
                }
            }
            __syncthreads();
            if (tid < P) sm.nms.key[tid] = v;
            __syncthreads();

            const bool shpath = (M <= MROW_SH);
            const int mwords = shpath ? MWORDS_SH : MWORDS;
            u32* mask = shpath ? sm.nms.masksh : &g_mask[bid * MROW * MWORDS];
            const int Wd = (M + 31) >> 5;

            // ---- ballot mask build: warp per row, 32 IoUs per step ----
            for (int i = wid; i < M; i += 32) {
                u64 ki = sm.nms.key[i];
                int pi = (int)(~(u32)ki);
                float4 bi = sm.nms.boxp[pi];
                float ai = (bi.z - bi.x + 1.0f) * (bi.w - bi.y + 1.0f);
                int w0 = (i + 1) >> 5;
                if (lane < w0) mask[i * mwords + lane] = 0;
                for (int w = w0; w < Wd; w++) {
                    int j = (w << 5) + lane;
                    bool hit = false;
                    if (j > i && j < M) {
                        u64 kj = sm.nms.key[j];
                        int pj = (int)(~(u32)kj);
                        float4 bj = sm.nms.boxp[pj];
                        float lx = fmaxf(bi.x, bj.x), ly = fmaxf(bi.y, bj.y);
                        float rx = fminf(bi.z, bj.z), ry = fminf(bi.w, bj.w);
                        float iw = fmaxf(rx - lx + 1.0f, 0.0f);
                        float ih = fmaxf(ry - ly + 1.0f, 0.0f);
                        float inter = iw * ih;
                        float aj = (bj.z - bj.x + 1.0f) * (bj.w - bj.y + 1.0f);
                        hit = (inter / (ai + aj - inter) > NMS_THRESH);
                    }
                    u32 bits = __ballot_sync(0xffffffffu, hit);
                    if (lane == 0) mask[i * mwords + w] = bits;
                }
            }
            __syncthreads();

            // ---- greedy resolve: warp 0, skip dead boxes via ffs ----
            if (tid < 32) {
                u32 kw = (lane < Wd) ? 0xffffffffu : 0u;
                int rem = M & 31;
                if (rem && lane == Wd - 1) kw = (1u << rem) - 1u;
                int i = 0;
                while (i < M) {
                    u32 w = __shfl_sync(0xffffffffu, kw, i >> 5);
                    u32 msk = w & (0xffffffffu << (i & 31));
                    if (msk == 0) { i = ((i >> 5) + 1) << 5; continue; }
                    i = ((i >> 5) << 5) + (__ffs(msk) - 1);
                    if (i >= M) break;
                    u32 rw = (lane < Wd) ? mask[i * mwords + lane] : 0u;
                    kw &= ~rw;
                    i += 1;
                }
                if (lane < Wd) sm.nms.keepw[lane] = kw;
            }
            __syncthreads();

            // ---- block-scan append + incremental global histogram ----
            if (tid == 0) {
                int run = 0;
                for (int w = 0; w < Wd; w++) {
                    sm.nms.wpfx[w] = run;
                    run += __popc(sm.nms.keepw[w]);
                }
                sm.nms.wpfx[Wd] = run;
                sm.nms.base = atomicAdd(&g_count, run);
            }
            __syncthreads();
            const int base = sm.nms.base;

            for (int j = tid; j < M; j += NTHREADS) {
                u32 kwj = sm.nms.keepw[j >> 5];
                if ((kwj >> (j & 31)) & 1u) {
                    int rank = sm.nms.wpfx[j >> 5] + __popc(kwj & ((1u << (j & 31)) - 1u));
                    int pos = base + rank;
                    u64 kj = sm.nms.key[j];
                    u32 sb = (u32)(kj >> 32);
                    int key = bid * N_PROP + j;      // reference flat index
                    g_cscore[pos] = __uint_as_float(sb);
                    g_ckey[pos]   = key;
                    g_boxkey[key] = sm.nms.boxp[(int)(~(u32)kj)];
                    atomicAdd(&g_hist[score_bin(sb)], 1);
                }
            }
        }
    }
    grid_sync();

    // ================= Phase C: block 0 top-100 =================
    if (bid != 0) return;

    const int K = g_count;
    const int target = (K < DET_PER_IMG) ? K : DET_PER_IMG;

    if (tid == 0) { sm.topk.bstar = 0; sm.topk.cnt = 0; }
    __syncthreads();

    // chunk sums from global histogram (already built in Phase B)
    const int CH = NBINS / NTHREADS;        // 4
    const int base = tid * CH;
    int cs[CH];
    int sum = 0;
    #pragma unroll
    for (int t = 0; t < CH; t++) { cs[t] = g_hist[base + t]; sum += cs[t]; }

    // hierarchical suffix scan (3 syncs)
    int v = sum;
    #pragma unroll
    for (int off = 1; off < 32; off <<= 1) {
        int t = __shfl_down_sync(0xffffffffu, v, off);
        if (lane + off < 32) v += t;
    }
    if (lane == 0) sm.topk.part[wid] = v;     // warp totals
    __syncthreads();
    if (tid < 32) {
        int wv = sm.topk.part[lane];
        #pragma unroll
        for (int off = 1; off < 32; off <<= 1) {
            int t = __shfl_down_sync(0xffffffffu, wv, off);
            if (lane + off < 32) wv += t;
        }
        sm.topk.part[32 + lane] = wv;         // suffix-inclusive over warp totals
    }
    __syncthreads();
    {
        int after_warp = (wid < 31) ? sm.topk.part[32 + wid + 1] : 0;
        int suf = (v - sum) + after_warp;     // chunks strictly after mine
        #pragma unroll
        for (int t = CH - 1; t >= 0; t--) {
            suf += cs[t];
            if (suf >= target) { atomicMax(&sm.topk.bstar, base + t); break; }
        }
    }
    __syncthreads();
    const int bstar = sm.topk.bstar;

    // compact candidates in bins >= b*
    for (int i = tid; i < K; i += NTHREADS) {
        u32 sb = __float_as_uint(g_cscore[i]);
        if (score_bin(sb) >= bstar) {
            int pos = atomicAdd(&sm.topk.cnt, 1);
            if (pos < TOPK_CAP)
                sm.topk.buf[pos] = ((u64)sb << 32) | (u32)(~g_ckey[i]);
        }
    }
    __syncthreads();
    const int C = sm.topk.cnt;

    if (C <= NTHREADS) {
        // register-resident hybrid bitonic, direct output
        int P2 = 32;
        while (P2 < C) P2 <<= 1;
        u64 v2 = (tid < C) ? sm.topk.buf[tid] : 0ULL;
        for (int k = 2; k <= P2; k <<= 1) {
            for (int j = k >> 1; j > 0; j >>= 1) {
                if (j >= 32) {
                    __syncthreads();
                    if (tid < P2) sm.topk.buf[tid] = v2;
                    __syncthreads();
                    if (tid < P2) {
                        u64 o = sm.topk.buf[tid ^ j];
                        bool takeMax = ((tid & k) == 0) == ((tid & j) == 0);
                        v2 = takeMax ? (v2 > o ? v2 : o) : (v2 < o ? v2 : o);
                    }
                } else {
                    u64 o = __shfl_xor_sync(0xffffffffu, v2, j);
                    bool takeMax = ((tid & k) == 0) == ((tid & j) == 0);
                    v2 = takeMax ? (v2 > o ? v2 : o) : (v2 < o ? v2 : o);
                }
            }
        }
        if (tid < DET_PER_IMG) {
            if (tid < C) {
                int key = (int)(~(u32)v2);
                float4 b = g_boxkey[key];
                out[tid] = __uint_as_float((u32)(v2 >> 32));
                out[DET_PER_IMG + tid * 4 + 0] = b.x;
                out[DET_PER_IMG + tid * 4 + 1] = b.y;
                out[DET_PER_IMG + tid * 4 + 2] = b.z;
                out[DET_PER_IMG + tid * 4 + 3] = b.w;
                out[DET_PER_IMG * 5 + tid] = (float)(key / N_PROP + 1);
            } else {
                out[tid] = 0.0f;
                out[DET_PER_IMG + tid * 4 + 0] = 0.0f;
                out[DET_PER_IMG + tid * 4 + 1] = 0.0f;
                out[DET_PER_IMG + tid * 4 + 2] = 0.0f;
                out[DET_PER_IMG + tid * 4 + 3] = 0.0f;
                out[DET_PER_IMG * 5 + tid] = 0.0f;
            }
        }
        return;
    }

    if (C <= TOPK_CAP) {
        // shared bitonic over up to 2048 elements
        int P2 = 128;
        while (P2 < C) P2 <<= 1;
        for (int i = C + tid; i < P2; i += NTHREADS) sm.topk.buf[i] = 0ULL;
        __syncthreads();

        for (int k = 2; k <= P2; k <<= 1) {
            for (int j = k >> 1; j > 0; j >>= 1) {
                for (int i = tid; i < P2; i += NTHREADS) {
                    int ixj = i ^ j;
                    if (ixj > i) {
                        u64 a = sm.topk.buf[i], b = sm.topk.buf[ixj];
                        bool up = ((i & k) == 0);
                        if (up ? (a < b) : (a > b)) { sm.topk.buf[i] = b; sm.topk.buf[ixj] = a; }
                    }
                }
                __syncthreads();
            }
        }

        for (int r = tid; r < DET_PER_IMG; r += NTHREADS) {
            if (r < C) {
                u64 vv = sm.topk.buf[r];
                int key = (int)(~(u32)vv);
                float4 b = g_boxkey[key];
                out[r] = __uint_as_float((u32)(vv >> 32));
                out[DET_PER_IMG + r * 4 + 0] = b.x;
                out[DET_PER_IMG + r * 4 + 1] = b.y;
                out[DET_PER_IMG + r * 4 + 2] = b.z;
                out[DET_PER_IMG + r * 4 + 3] = b.w;
                out[DET_PER_IMG * 5 + r] = (float)(key / N_PROP + 1);
            } else {
                out[r] = 0.0f;
                out[DET_PER_IMG + r * 4 + 0] = 0.0f;
                out[DET_PER_IMG + r * 4 + 1] = 0.0f;
                out[DET_PER_IMG + r * 4 + 2] = 0.0f;
                out[DET_PER_IMG + r * 4 + 3] = 0.0f;
                out[DET_PER_IMG * 5 + r] = 0.0f;
            }
        }
        return;
    }

    // -------- fallback: repeated global argmax (C > TOPK_CAP, pathological) ------
    u64* r_v = sm.topk.buf;
    int* r_i = (int*)(sm.topk.buf + NTHREADS);
    __syncthreads();
    for (int r = 0; r < DET_PER_IMG; r++) {
        u64 bv = 0ULL; int bi = -1;
        for (int i = tid; i < K; i += NTHREADS) {
            u32 sb = __float_as_uint(g_cscore[i]);
            u64 vv = ((u64)sb << 32) | (u32)(~g_ckey[i]);
            if (vv > bv) { bv = vv; bi = i; }
        }
        r_v[tid] = bv; r_i[tid] = bi;
        __syncthreads();
        for (int off = NTHREADS >> 1; off > 0; off >>= 1) {
            if (tid < off) {
                if (r_v[tid + off] > r_v[tid]) { r_v[tid] = r_v[tid + off]; r_i[tid] = r_i[tid + off]; }
            }
            __syncthreads();
        }
        if (tid == 0) {
            int idx = r_i[0];
            u64 vv = r_v[0];
            int key = (int)(~(u32)vv);
            float4 b = g_boxkey[key];
            out[r] = __uint_as_float((u32)(vv >> 32));
            out[DET_PER_IMG + r * 4 + 0] = b.x;
            out[DET_PER_IMG + r * 4 + 1] = b.y;
            out[DET_PER_IMG + r * 4 + 2] = b.z;
            out[DET_PER_IMG + r * 4 + 3] = b.w;
            out[DET_PER_IMG * 5 + r] = (float)(key / N_PROP + 1);
            g_cscore[idx] = 0.0f;
        }
        __syncthreads();
    }
}

extern "C" void kernel_launch(void* const* d_in, const int* in_sizes, int n_in,
                              void* d_out, int out_size) {
    const float* logits = (const float*)d_in[0];   // [1000, 81]
    const float* deltas = (const float*)d_in[1];   // [1000, 324]
    const float* pboxes = (const float*)d_in[2];   // [1000, 4]
    const int*   ih     = (const int*)d_in[3];     // scalar
    const int*   iw     = (const int*)d_in[4];     // scalar

    fused_kernel<<<NBLOCKS, NTHREADS>>>(logits, deltas, pboxes, ih, iw, (float*)d_out);
}

// round 12
// speedup vs baseline: 1.4483x; 1.0350x over previous
#include <cuda_runtime.h>
#include <math.h>

#define N_PROP 1000
#define NUM_CLASSES 81
#define NUM_FG 80
#define SCORE_THRESH 0.05f
#define NMS_THRESH 0.5f
#define DET_PER_IMG 100
#define BBOX_XFORM_CLIP 4.135166556742356f
#define CAND_MAX (N_PROP * NUM_FG)

#define NBLOCKS 80
#define NTHREADS 512
#define NWARPS (NTHREADS / 32)

#define PROB_PITCH 1024      // padded row pitch for transposed probs

#define MROW 1024            // global-mask rows (fallback, M > 256)
#define MWORDS 32            // 1024 bits
#define MROW_SH 256          // shared-mask rows (fast path)
#define MWORDS_SH 8          // 256 bits

#define NBINS 4096
#define TOPK_CAP 2048

typedef unsigned long long u64;
typedef unsigned int u32;

// ---------- device scratch (no allocations allowed) ----------
__device__ float  g_probT[NUM_CLASSES * PROB_PITCH];   // [class][proposal]
__device__ int    g_count;
__device__ int    g_hist[NBINS];                       // global histogram (built in Phase B)
__device__ float  g_cscore[CAND_MAX];
__device__ int    g_ckey[CAND_MAX];
__device__ float4 g_boxkey[CAND_MAX];
__device__ u32    g_mask[NUM_FG * MROW * MWORDS];      // fallback mask (M > 256)
__device__ float  g_dummy;                             // prefetch sink (never read)

// self-resetting grid barrier state (gen is monotonic across graph replays)
__device__ unsigned int g_bar_count = 0;
__device__ unsigned int g_bar_gen   = 0;

__device__ __forceinline__ void grid_sync() {
    __threadfence();
    __syncthreads();
    if (threadIdx.x == 0) {
        unsigned gen = *((volatile unsigned*)&g_bar_gen);
        unsigned old = atomicInc(&g_bar_count, NBLOCKS - 1);   // wraps to 0 -> self-reset
        if (old == NBLOCKS - 1) {
            atomicAdd(&g_bar_gen, 1);
        } else {
            while (*((volatile unsigned*)&g_bar_gen) == gen) {}
        }
    }
    __syncthreads();
    __threadfence();
}

__device__ __forceinline__ float load_dim(const int* p) {
    int vi = *p;
    if (vi > 0 && vi < 100000) return (float)vi;
    return __int_as_float(vi);
}

__device__ __forceinline__ int score_bin(u32 bits) {
    int b = (int)(bits >> 14) - 0xF400;      // scores in (0.05, 1] -> positive bins
    return min(NBINS - 1, max(0, b));
}

// ---------- shared memory union across phases ----------
struct SmemNMS {
    u64    key[1024];        // (score_bits<<32) | ~prop_idx
    float4 boxp[1024];       // box indexed by PROPOSAL id (no sort payload)
    u32    masksh[MROW_SH * MWORDS_SH];
    u32    keepw[MWORDS];
    int    wpfx[MWORDS + 1];
    int    base;
    int    cnt;
};
struct SmemTopk {
    u64 buf[TOPK_CAP];
    int part[NTHREADS];
    int bstar;
    int cnt;
};
union SmemAll {
    SmemNMS  nms;
    SmemTopk topk;
};

__global__ void __launch_bounds__(NTHREADS, 1)
fused_kernel(const float* __restrict__ logits,
             const float* __restrict__ deltas,
             const float* __restrict__ pboxes,
             const int* __restrict__ ih_p,
             const int* __restrict__ iw_p,
             float* __restrict__ out) {
    __shared__ SmemAll sm;
    const int tid  = threadIdx.x;
    const int bid  = blockIdx.x;
    const int lane = tid & 31;
    const int wid  = tid >> 5;

    // ====== Phase A: lse + transposed softmax probs (warp per proposal) ======
    if (bid == 0 && tid == 0) g_count = 0;
    {
        int z = bid * NTHREADS + tid;
        if (z < NBINS) g_hist[z] = 0;
    }
    {
        const int gw = bid * NWARPS + wid;              // 0..1279: single pass
        if (gw < N_PROP) {
            const int p = gw;
            const float* row = logits + p * NUM_CLASSES;
            float v0 = row[lane];
            float v1 = row[lane + 32];
            bool has2 = (lane + 64 < NUM_CLASSES);
            float v2 = has2 ? row[lane + 64] : -INFINITY;
            float m = fmaxf(fmaxf(v0, v1), v2);
            #pragma unroll
            for (int o = 16; o > 0; o >>= 1) m = fmaxf(m, __shfl_xor_sync(0xffffffffu, m, o));
            float s = expf(v0 - m) + expf(v1 - m);
            if (has2) s += expf(v2 - m);
            #pragma unroll
            for (int o = 16; o > 0; o >>= 1) s += __shfl_xor_sync(0xffffffffu, s, o);
            float lse = m + logf(s);                    // same on all lanes
            g_probT[lane * PROB_PITCH + p]        = expf(v0 - lse);
            g_probT[(lane + 32) * PROB_PITCH + p] = expf(v1 - lse);
            if (has2)
                g_probT[(lane + 64) * PROB_PITCH + p] = expf(v2 - lse);
        } else {
            // idle warps: warm L2 with deltas + pboxes for Phase B
            const int tstride = (NBLOCKS * NWARPS - N_PROP) * 32;       // 8960
            int tidx = (gw - N_PROP) * 32 + lane;
            const float4* dl4 = (const float4*)deltas;
            float acc = 0.0f;
            for (int i = tidx; i < N_PROP * NUM_CLASSES; i += tstride) {
                float4 d = dl4[i];
                acc += d.x + d.y + d.z + d.w;
            }
            if (tidx < N_PROP) {
                float4 b = ((const float4*)pboxes)[tidx];
                acc += b.x;
            }
            if (acc == 1.0e38f) g_dummy = acc;          // never true; defeats DCE
        }
    }
    grid_sync();

    // ================= Phase B: per-class decode + sort + NMS =================
    {
        const int c = bid + 1;               // foreground class 1..80
        if (tid == 0) sm.nms.cnt = 0;
        __syncthreads();

        const float W = load_dim(iw_p) - 1.0f;
        const float H = load_dim(ih_p) - 1.0f;
        const float* prow = g_probT + c * PROB_PITCH;
        const float4* pb4 = (const float4*)pboxes;
        const float4* dl4 = (const float4*)deltas;

        for (int p = tid; p < N_PROP; p += NTHREADS) {
            float sc = prow[p];
            if (sc > SCORE_THRESH) {
                float4 pb = pb4[p];
                float w  = pb.z - pb.x + 1.0f,  h  = pb.w - pb.y + 1.0f;
                float cx = pb.x + 0.5f * w,     cy = pb.y + 0.5f * h;
                float4 d = dl4[p * NUM_CLASSES + c];
                float dx = d.x / 10.0f;
                float dy = d.y / 10.0f;
                float dw = fminf(d.z / 5.0f, BBOX_XFORM_CLIP);
                float dh = fminf(d.w / 5.0f, BBOX_XFORM_CLIP);
                float pcx = dx * w + cx, pcy = dy * h + cy;
                float pw  = expf(dw) * w, ph = expf(dh) * h;
                float bx1 = fminf(fmaxf(pcx - 0.5f * pw, 0.0f), W);
                float by1 = fminf(fmaxf(pcy - 0.5f * ph, 0.0f), H);
                float bx2 = fminf(fmaxf(pcx + 0.5f * pw - 1.0f, 0.0f), W);
                float by2 = fminf(fmaxf(pcy + 0.5f * ph - 1.0f, 0.0f), H);
                int slot = atomicAdd(&sm.nms.cnt, 1);
                sm.nms.key[slot] = ((u64)__float_as_uint(sc) << 32) | (u32)(~p);
                sm.nms.boxp[p]   = make_float4(bx1, by1, bx2, by2);
            }
        }
        __syncthreads();
        const int M = sm.nms.cnt;

        if (M > 0) {
            int P = 32;
            while (P < M) P <<= 1;

            if (P <= NTHREADS) {
                // ---- keys-only hybrid bitonic sort, register-resident ----
                u64 v = (tid < M) ? sm.nms.key[tid] : 0ULL;
                for (int k = 2; k <= P; k <<= 1) {
                    for (int j = k >> 1; j > 0; j >>= 1) {
                        if (j >= 32) {
                            __syncthreads();
                            if (tid < P) sm.nms.key[tid] = v;
                            __syncthreads();
                            if (tid < P) {
                                u64 o = sm.nms.key[tid ^ j];
                                bool takeMax = ((tid & k) == 0) == ((tid & j) == 0);
                                v = takeMax ? (v > o ? v : o) : (v < o ? v : o);
                            }
                        } else {
                            u64 o = __shfl_xor_sync(0xffffffffu, v, j);
                            bool takeMax = ((tid & k) == 0) == ((tid & j) == 0);
                            v = takeMax ? (v > o ? v : o) : (v < o ? v : o);
                        }
                    }
                }
                __syncthreads();
                if (tid < P) sm.nms.key[tid] = v;
                __syncthreads();
            } else {
                // ---- fallback: shared keys-only bitonic (M > NTHREADS, rare) ----
                for (int i = M + tid; i < P; i += NTHREADS) sm.nms.key[i] = 0ULL;
                __syncthreads();
                for (int k = 2; k <= P; k <<= 1) {
                    for (int j = k >> 1; j > 0; j >>= 1) {
                        for (int i = tid; i < P; i += NTHREADS) {
                            int ixj = i ^ j;
                            if (ixj > i) {
                                u64 a = sm.nms.key[i], b = sm.nms.key[ixj];
                                bool up = ((i & k) == 0);
                                if (up ? (a < b) : (a > b)) { sm.nms.key[i] = b; sm.nms.key[ixj] = a; }
                            }
                        }
                        __syncthreads();
                    }
                }
            }

            const bool shpath = (M <= MROW_SH);
            const int mwords = shpath ? MWORDS_SH : MWORDS;
            u32* mask = shpath ? sm.nms.masksh : &g_mask[bid * MROW * MWORDS];
            const int Wd = (M + 31) >> 5;

            // ---- ballot mask build: warp per row ----
            for (int i = wid; i < M; i += NWARPS) {
                u64 ki = sm.nms.key[i];
                int pi = (int)(~(u32)ki);
                float4 bi = sm.nms.boxp[pi];
                float ai = (bi.z - bi.x + 1.0f) * (bi.w - bi.y + 1.0f);
                int w0 = (i + 1) >> 5;
                if (lane < w0) mask[i * mwords + lane] = 0;
                for (int w = w0; w < Wd; w++) {
                    int j = (w << 5) + lane;
                    bool hit = false;
                    if (j > i && j < M) {
                        u64 kj = sm.nms.key[j];
                        int pj = (int)(~(u32)kj);
                        float4 bj = sm.nms.boxp[pj];
                        float lx = fmaxf(bi.x, bj.x), ly = fmaxf(bi.y, bj.y);
                        float rx = fminf(bi.z, bj.z), ry = fminf(bi.w, bj.w);
                        float iw = fmaxf(rx - lx + 1.0f, 0.0f);
                        float ih = fmaxf(ry - ly + 1.0f, 0.0f);
                        float inter = iw * ih;
                        float aj = (bj.z - bj.x + 1.0f) * (bj.w - bj.y + 1.0f);
                        hit = (inter / (ai + aj - inter) > NMS_THRESH);
                    }
                    u32 bits = __ballot_sync(0xffffffffu, hit);
                    if (lane == 0) mask[i * mwords + w] = bits;
                }
            }
            __syncthreads();

            // ---- greedy resolve: warp 0, skip dead boxes via ffs ----
            if (tid < 32) {
                u32 kw = (lane < Wd) ? 0xffffffffu : 0u;
                int rem = M & 31;
                if (rem && lane == Wd - 1) kw = (1u << rem) - 1u;
                int i = 0;
                while (i < M) {
                    u32 w = __shfl_sync(0xffffffffu, kw, i >> 5);
                    u32 msk = w & (0xffffffffu << (i & 31));
                    if (msk == 0) { i = ((i >> 5) + 1) << 5; continue; }
                    i = ((i >> 5) << 5) + (__ffs(msk) - 1);
                    if (i >= M) break;
                    u32 rw = (lane < Wd) ? mask[i * mwords + lane] : 0u;
                    kw &= ~rw;
                    i += 1;
                }
                if (lane < Wd) sm.nms.keepw[lane] = kw;
            }
            __syncthreads();

            // ---- block-scan append + incremental global histogram ----
            if (tid == 0) {
                int run = 0;
                for (int w = 0; w < Wd; w++) {
                    sm.nms.wpfx[w] = run;
                    run += __popc(sm.nms.keepw[w]);
                }
                sm.nms.wpfx[Wd] = run;
                sm.nms.base = atomicAdd(&g_count, run);
            }
            __syncthreads();
            const int base = sm.nms.base;

            for (int j = tid; j < M; j += NTHREADS) {
                u32 kwj = sm.nms.keepw[j >> 5];
                if ((kwj >> (j & 31)) & 1u) {
                    int rank = sm.nms.wpfx[j >> 5] + __popc(kwj & ((1u << (j & 31)) - 1u));
                    int pos = base + rank;
                    u64 kj = sm.nms.key[j];
                    u32 sb = (u32)(kj >> 32);
                    int key = bid * N_PROP + j;      // reference flat index
                    g_cscore[pos] = __uint_as_float(sb);
                    g_ckey[pos]   = key;
                    g_boxkey[key] = sm.nms.boxp[(int)(~(u32)kj)];
                    atomicAdd(&g_hist[score_bin(sb)], 1);
                }
            }
        }
    }
    grid_sync();

    // ================= Phase C: block 0 top-100 =================
    if (bid != 0) return;

    const int K = g_count;
    const int target = (K < DET_PER_IMG) ? K : DET_PER_IMG;

    if (tid == 0) { sm.topk.bstar = 0; sm.topk.cnt = 0; }
    __syncthreads();

    // chunk sums from global histogram (already built in Phase B)
    const int CH = NBINS / NTHREADS;        // 8
    const int base = tid * CH;
    int cs[CH];
    int sum = 0;
    #pragma unroll
    for (int t = 0; t < CH; t++) { cs[t] = g_hist[base + t]; sum += cs[t]; }

    // hierarchical suffix scan (3 syncs)
    int v = sum;
    #pragma unroll
    for (int off = 1; off < 32; off <<= 1) {
        int t = __shfl_down_sync(0xffffffffu, v, off);
        if (lane + off < 32) v += t;
    }
    if (lane == 0) sm.topk.part[wid] = v;     // warp totals (NWARPS entries)
    __syncthreads();
    if (tid < 32) {
        int wv = (lane < NWARPS) ? sm.topk.part[lane] : 0;
        #pragma unroll
        for (int off = 1; off < NWARPS; off <<= 1) {
            int t = __shfl_down_sync(0xffffffffu, wv, off);
            if (lane + off < NWARPS) wv += t;
        }
        if (lane < NWARPS) sm.topk.part[NWARPS + lane] = wv;   // suffix-incl warp totals
    }
    __syncthreads();
    {
        int after_warp = (wid < NWARPS - 1) ? sm.topk.part[NWARPS + wid + 1] : 0;
        int suf = (v - sum) + after_warp;     // chunks strictly after mine
        #pragma unroll
        for (int t = CH - 1; t >= 0; t--) {
            suf += cs[t];
            if (suf >= target) { atomicMax(&sm.topk.bstar, base + t); break; }
        }
    }
    __syncthreads();
    const int bstar = sm.topk.bstar;

    // compact candidates in bins >= b*
    for (int i = tid; i < K; i += NTHREADS) {
        u32 sb = __float_as_uint(g_cscore[i]);
        if (score_bin(sb) >= bstar) {
            int pos = atomicAdd(&sm.topk.cnt, 1);
            if (pos < TOPK_CAP)
                sm.topk.buf[pos] = ((u64)sb << 32) | (u32)(~g_ckey[i]);
        }
    }
    __syncthreads();
    const int C = sm.topk.cnt;

    if (C <= NTHREADS) {
        // register-resident hybrid bitonic, direct output
        int P2 = 32;
        while (P2 < C) P2 <<= 1;
        u64 v2 = (tid < C) ? sm.topk.buf[tid] : 0ULL;
        for (int k = 2; k <= P2; k <<= 1) {
            for (int j = k >> 1; j > 0; j >>= 1) {
                if (j >= 32) {
                    __syncthreads();
                    if (tid < P2) sm.topk.buf[tid] = v2;
                    __syncthreads();
                    if (tid < P2) {
                        u64 o = sm.topk.buf[tid ^ j];
                        bool takeMax = ((tid & k) == 0) == ((tid & j) == 0);
                        v2 = takeMax ? (v2 > o ? v2 : o) : (v2 < o ? v2 : o);
                    }
                } else {
                    u64 o = __shfl_xor_sync(0xffffffffu, v2, j);
                    bool takeMax = ((tid & k) == 0) == ((tid & j) == 0);
                    v2 = takeMax ? (v2 > o ? v2 : o) : (v2 < o ? v2 : o);
                }
            }
        }
        if (tid < DET_PER_IMG) {
            if (tid < C) {
                int key = (int)(~(u32)v2);
                float4 b = g_boxkey[key];
                out[tid] = __uint_as_float((u32)(v2 >> 32));
                out[DET_PER_IMG + tid * 4 + 0] = b.x;
                out[DET_PER_IMG + tid * 4 + 1] = b.y;
                out[DET_PER_IMG + tid * 4 + 2] = b.z;
                out[DET_PER_IMG + tid * 4 + 3] = b.w;
                out[DET_PER_IMG * 5 + tid] = (float)(key / N_PROP + 1);
            } else {
                out[tid] = 0.0f;
                out[DET_PER_IMG + tid * 4 + 0] = 0.0f;
                out[DET_PER_IMG + tid * 4 + 1] = 0.0f;
                out[DET_PER_IMG + tid * 4 + 2] = 0.0f;
                out[DET_PER_IMG + tid * 4 + 3] = 0.0f;
                out[DET_PER_IMG * 5 + tid] = 0.0f;
            }
        }
        return;
    }

    if (C <= TOPK_CAP) {
        // shared bitonic over up to 2048 elements
        int P2 = 1024;
        while (P2 < C) P2 <<= 1;
        for (int i = C + tid; i < P2; i += NTHREADS) sm.topk.buf[i] = 0ULL;
        __syncthreads();

        for (int k = 2; k <= P2; k <<= 1) {
            for (int j = k >> 1; j > 0; j >>= 1) {
                for (int i = tid; i < P2; i += NTHREADS) {
                    int ixj = i ^ j;
                    if (ixj > i) {
                        u64 a = sm.topk.buf[i], b = sm.topk.buf[ixj];
                        bool up = ((i & k) == 0);
                        if (up ? (a < b) : (a > b)) { sm.topk.buf[i] = b; sm.topk.buf[ixj] = a; }
                    }
                }
                __syncthreads();
            }
        }

        for (int r = tid; r < DET_PER_IMG; r += NTHREADS) {
            if (r < C) {
                u64 vv = sm.topk.buf[r];
                int key = (int)(~(u32)vv);
                float4 b = g_boxkey[key];
                out[r] = __uint_as_float((u32)(vv >> 32));
                out[DET_PER_IMG + r * 4 + 0] = b.x;
                out[DET_PER_IMG + r * 4 + 1] = b.y;
                out[DET_PER_IMG + r * 4 + 2] = b.z;
                out[DET_PER_IMG + r * 4 + 3] = b.w;
                out[DET_PER_IMG * 5 + r] = (float)(key / N_PROP + 1);
            } else {
                out[r] = 0.0f;
                out[DET_PER_IMG + r * 4 + 0] = 0.0f;
                out[DET_PER_IMG + r * 4 + 1] = 0.0f;
                out[DET_PER_IMG + r * 4 + 2] = 0.0f;
                out[DET_PER_IMG + r * 4 + 3] = 0.0f;
                out[DET_PER_IMG * 5 + r] = 0.0f;
            }
        }
        return;
    }

    // -------- fallback: repeated global argmax (C > TOPK_CAP, pathological) ------
    u64* r_v = sm.topk.buf;
    int* r_i = (int*)(sm.topk.buf + NTHREADS);
    __syncthreads();
    for (int r = 0; r < DET_PER_IMG; r++) {
        u64 bv = 0ULL; int bi = -1;
        for (int i = tid; i < K; i += NTHREADS) {
            u32 sb = __float_as_uint(g_cscore[i]);
            u64 vv = ((u64)sb << 32) | (u32)(~g_ckey[i]);
            if (vv > bv) { bv = vv; bi = i; }
        }
        r_v[tid] = bv; r_i[tid] = bi;
        __syncthreads();
        for (int off = NTHREADS >> 1; off > 0; off >>= 1) {
            if (tid < off) {
                if (r_v[tid + off] > r_v[tid]) { r_v[tid] = r_v[tid + off]; r_i[tid] = r_i[tid + off]; }
            }
            __syncthreads();
        }
        if (tid == 0) {
            int idx = r_i[0];
            u64 vv = r_v[0];
            int key = (int)(~(u32)vv);
            float4 b = g_boxkey[key];
            out[r] = __uint_as_float((u32)(vv >> 32));
            out[DET_PER_IMG + r * 4 + 0] = b.x;
            out[DET_PER_IMG + r * 4 + 1] = b.y;
            out[DET_PER_IMG + r * 4 + 2] = b.z;
            out[DET_PER_IMG + r * 4 + 3] = b.w;
            out[DET_PER_IMG * 5 + r] = (float)(key / N_PROP + 1);
            g_cscore[idx] = 0.0f;
        }
        __syncthreads();
    }
}

extern "C" void kernel_launch(void* const* d_in, const int* in_sizes, int n_in,
                              void* d_out, int out_size) {
    const float* logits = (const float*)d_in[0];   // [1000, 81]
    const float* deltas = (const float*)d_in[1];   // [1000, 324]
    const float* pboxes = (const float*)d_in[2];   // [1000, 4]
    const int*   ih     = (const int*)d_in[3];     // scalar
    const int*   iw     = (const int*)d_in[4];     // scalar

    fused_kernel<<<NBLOCKS, NTHREADS>>>(logits, deltas, pboxes, ih, iw, (float*)d_out);
}

// round 13
// speedup vs baseline: 1.4789x; 1.0211x over previous
#include <cuda_runtime.h>
#include <math.h>

#define N_PROP 1000
#define NUM_CLASSES 81
#define NUM_FG 80
#define SCORE_THRESH 0.05f
#define NMS_THRESH 0.5f
#define DET_PER_IMG 100
#define BBOX_XFORM_CLIP 4.135166556742356f
#define CAND_MAX (N_PROP * NUM_FG)

#define NBLOCKS 80
#define NTHREADS 512
#define NWARPS (NTHREADS / 32)

#define PROB_PITCH 1024      // padded row pitch for transposed probs

#define MROW 1024            // global-mask rows (fallback, M > 256)
#define MWORDS 32            // 1024 bits
#define MROW_SH 256          // shared-mask rows (fast path)
#define MWORDS_SH 8          // 256 bits

#define NBINS 4096
#define TOPK_CAP 2048

typedef unsigned long long u64;
typedef unsigned int u32;

// ---------- device scratch (no allocations allowed) ----------
__device__ float  g_probT[NUM_CLASSES * PROB_PITCH];   // [class][proposal]
__device__ int    g_count;
__device__ int    g_hist[NBINS];                       // global histogram (built in Phase B)
__device__ float  g_cscore[CAND_MAX];
__device__ int    g_ckey[CAND_MAX];
__device__ float4 g_boxkey[CAND_MAX];
__device__ u32    g_mask[NUM_FG * MROW * MWORDS];      // fallback mask (M > 256)
__device__ float  g_dummy;                             // prefetch sink (never read)

// barrier + completion counters (wrap -> self-reset across graph replays)
__device__ unsigned int g_bar_count = 0;
__device__ unsigned int g_bar_gen   = 0;
__device__ unsigned int g_done      = 0;

__device__ __forceinline__ void grid_sync() {
    __threadfence();
    __syncthreads();
    if (threadIdx.x == 0) {
        unsigned gen = *((volatile unsigned*)&g_bar_gen);
        unsigned old = atomicInc(&g_bar_count, NBLOCKS - 1);   // wraps to 0 -> self-reset
        if (old == NBLOCKS - 1) {
            atomicAdd(&g_bar_gen, 1);
        } else {
            while (*((volatile unsigned*)&g_bar_gen) == gen) {}
        }
    }
    __syncthreads();
    __threadfence();
}

__device__ __forceinline__ float load_dim(const int* p) {
    int vi = *p;
    if (vi > 0 && vi < 100000) return (float)vi;
    return __int_as_float(vi);
}

__device__ __forceinline__ int score_bin(u32 bits) {
    int b = (int)(bits >> 14) - 0xF400;      // scores in (0.05, 1] -> positive bins
    return min(NBINS - 1, max(0, b));
}

// ---------- shared memory union across phases ----------
struct SmemNMS {
    u64    key[1024];        // (score_bits<<32) | ~prop_idx
    float4 boxp[1024];       // box indexed by PROPOSAL id (no sort payload)
    u32    masksh[MROW_SH * MWORDS_SH];
    u32    keepw[MWORDS];
    int    wpfx[MWORDS + 1];
    int    base;
    int    cnt;
};
struct SmemTopk {
    u64 buf[TOPK_CAP];
    int part[NTHREADS];
    int bstar;
    int cnt;
};
union SmemAll {
    SmemNMS  nms;
    SmemTopk topk;
};

__global__ void __launch_bounds__(NTHREADS, 1)
fused_kernel(const float* __restrict__ logits,
             const float* __restrict__ deltas,
             const float* __restrict__ pboxes,
             const int* __restrict__ ih_p,
             const int* __restrict__ iw_p,
             float* __restrict__ out) {
    __shared__ SmemAll sm;
    __shared__ int s_last;
    const int tid  = threadIdx.x;
    const int bid  = blockIdx.x;
    const int lane = tid & 31;
    const int wid  = tid >> 5;

    // ====== Phase A: lse + transposed softmax probs (warp per proposal) ======
    if (bid == 0 && tid == 0) g_count = 0;
    {
        int z = bid * NTHREADS + tid;
        if (z < NBINS) g_hist[z] = 0;
    }
    {
        const int gw = bid * NWARPS + wid;              // 0..1279: single pass
        if (gw < N_PROP) {
            const int p = gw;
            const float* row = logits + p * NUM_CLASSES;
            float v0 = row[lane];
            float v1 = row[lane + 32];
            bool has2 = (lane + 64 < NUM_CLASSES);
            float v2 = has2 ? row[lane + 64] : -INFINITY;
            float m = fmaxf(fmaxf(v0, v1), v2);
            #pragma unroll
            for (int o = 16; o > 0; o >>= 1) m = fmaxf(m, __shfl_xor_sync(0xffffffffu, m, o));
            float s = expf(v0 - m) + expf(v1 - m);
            if (has2) s += expf(v2 - m);
            #pragma unroll
            for (int o = 16; o > 0; o >>= 1) s += __shfl_xor_sync(0xffffffffu, s, o);
            float lse = m + logf(s);                    // same on all lanes
            g_probT[lane * PROB_PITCH + p]        = expf(v0 - lse);
            g_probT[(lane + 32) * PROB_PITCH + p] = expf(v1 - lse);
            if (has2)
                g_probT[(lane + 64) * PROB_PITCH + p] = expf(v2 - lse);
        } else {
            // idle warps: warm L2 with deltas + pboxes for Phase B
            const int tstride = (NBLOCKS * NWARPS - N_PROP) * 32;       // 8960
            int tidx = (gw - N_PROP) * 32 + lane;
            const float4* dl4 = (const float4*)deltas;
            float acc = 0.0f;
            for (int i = tidx; i < N_PROP * NUM_CLASSES; i += tstride) {
                float4 d = dl4[i];
                acc += d.x + d.y + d.z + d.w;
            }
            if (tidx < N_PROP) {
                float4 b = ((const float4*)pboxes)[tidx];
                acc += b.x;
            }
            if (acc == 1.0e38f) g_dummy = acc;          // never true; defeats DCE
        }
    }
    grid_sync();

    // ================= Phase B: per-class decode + sort + NMS =================
    {
        const int c = bid + 1;               // foreground class 1..80
        if (tid == 0) sm.nms.cnt = 0;
        __syncthreads();

        const float W = load_dim(iw_p) - 1.0f;
        const float H = load_dim(ih_p) - 1.0f;
        const float* prow = g_probT + c * PROB_PITCH;
        const float4* pb4 = (const float4*)pboxes;
        const float4* dl4 = (const float4*)deltas;

        for (int p = tid; p < N_PROP; p += NTHREADS) {
            float sc = prow[p];
            float4 pb = pb4[p];                     // independent of sc -> parallel
            float4 d  = dl4[p * NUM_CLASSES + c];   // independent of sc -> parallel
            if (sc > SCORE_THRESH) {
                float w  = pb.z - pb.x + 1.0f,  h  = pb.w - pb.y + 1.0f;
                float cx = pb.x + 0.5f * w,     cy = pb.y + 0.5f * h;
                float dx = d.x / 10.0f;
                float dy = d.y / 10.0f;
                float dw = fminf(d.z / 5.0f, BBOX_XFORM_CLIP);
                float dh = fminf(d.w / 5.0f, BBOX_XFORM_CLIP);
                float pcx = dx * w + cx, pcy = dy * h + cy;
                float pw  = expf(dw) * w, ph = expf(dh) * h;
                float bx1 = fminf(fmaxf(pcx - 0.5f * pw, 0.0f), W);
                float by1 = fminf(fmaxf(pcy - 0.5f * ph, 0.0f), H);
                float bx2 = fminf(fmaxf(pcx + 0.5f * pw - 1.0f, 0.0f), W);
                float by2 = fminf(fmaxf(pcy + 0.5f * ph - 1.0f, 0.0f), H);
                int slot = atomicAdd(&sm.nms.cnt, 1);
                sm.nms.key[slot] = ((u64)__float_as_uint(sc) << 32) | (u32)(~p);
                sm.nms.boxp[p]   = make_float4(bx1, by1, bx2, by2);
            }
        }
        __syncthreads();
        const int M = sm.nms.cnt;

        if (M > 0) {
            int P = 32;
            while (P < M) P <<= 1;

            if (P <= NTHREADS) {
                // ---- keys-only hybrid bitonic sort, register-resident ----
                u64 v = (tid < M) ? sm.nms.key[tid] : 0ULL;
                for (int k = 2; k <= P; k <<= 1) {
                    for (int j = k >> 1; j > 0; j >>= 1) {
                        if (j >= 32) {
                            __syncthreads();
                            if (tid < P) sm.nms.key[tid] = v;
                            __syncthreads();
                            if (tid < P) {
                                u64 o = sm.nms.key[tid ^ j];
                                bool takeMax = ((tid & k) == 0) == ((tid & j) == 0);
                                v = takeMax ? (v > o ? v : o) : (v < o ? v : o);
                            }
                        } else {
                            u64 o = __shfl_xor_sync(0xffffffffu, v, j);
                            bool takeMax = ((tid & k) == 0) == ((tid & j) == 0);
                            v = takeMax ? (v > o ? v : o) : (v < o ? v : o);
                        }
                    }
                }
                __syncthreads();
                if (tid < P) sm.nms.key[tid] = v;
                __syncthreads();
            } else {
                // ---- fallback: shared keys-only bitonic (M > NTHREADS, rare) ----
                for (int i = M + tid; i < P; i += NTHREADS) sm.nms.key[i] = 0ULL;
                __syncthreads();
                for (int k = 2; k <= P; k <<= 1) {
                    for (int j = k >> 1; j > 0; j >>= 1) {
                        for (int i = tid; i < P; i += NTHREADS) {
                            int ixj = i ^ j;
                            if (ixj > i) {
                                u64 a = sm.nms.key[i], b = sm.nms.key[ixj];
                                bool up = ((i & k) == 0);
                                if (up ? (a < b) : (a > b)) { sm.nms.key[i] = b; sm.nms.key[ixj] = a; }
                            }
                        }
                        __syncthreads();
                    }
                }
            }

            const bool shpath = (M <= MROW_SH);
            const int mwords = shpath ? MWORDS_SH : MWORDS;
            u32* mask = shpath ? sm.nms.masksh : &g_mask[bid * MROW * MWORDS];
            const int Wd = (M + 31) >> 5;

            // ---- ballot mask build: warp per row ----
            for (int i = wid; i < M; i += NWARPS) {
                u64 ki = sm.nms.key[i];
                int pi = (int)(~(u32)ki);
                float4 bi = sm.nms.boxp[pi];
                float ai = (bi.z - bi.x + 1.0f) * (bi.w - bi.y + 1.0f);
                int w0 = (i + 1) >> 5;
                if (lane < w0) mask[i * mwords + lane] = 0;
                for (int w = w0; w < Wd; w++) {
                    int j = (w << 5) + lane;
                    bool hit = false;
                    if (j > i && j < M) {
                        u64 kj = sm.nms.key[j];
                        int pj = (int)(~(u32)kj);
                        float4 bj = sm.nms.boxp[pj];
                        float lx = fmaxf(bi.x, bj.x), ly = fmaxf(bi.y, bj.y);
                        float rx = fminf(bi.z, bj.z), ry = fminf(bi.w, bj.w);
                        float iw = fmaxf(rx - lx + 1.0f, 0.0f);
                        float ih = fmaxf(ry - ly + 1.0f, 0.0f);
                        float inter = iw * ih;
                        float aj = (bj.z - bj.x + 1.0f) * (bj.w - bj.y + 1.0f);
                        hit = (inter / (ai + aj - inter) > NMS_THRESH);
                    }
                    u32 bits = __ballot_sync(0xffffffffu, hit);
                    if (lane == 0) mask[i * mwords + w] = bits;
                }
            }
            __syncthreads();

            // ---- greedy resolve: warp 0, skip dead boxes via ffs ----
            if (tid < 32) {
                u32 kw = (lane < Wd) ? 0xffffffffu : 0u;
                int rem = M & 31;
                if (rem && lane == Wd - 1) kw = (1u << rem) - 1u;
                int i = 0;
                while (i < M) {
                    u32 w = __shfl_sync(0xffffffffu, kw, i >> 5);
                    u32 msk = w & (0xffffffffu << (i & 31));
                    if (msk == 0) { i = ((i >> 5) + 1) << 5; continue; }
                    i = ((i >> 5) << 5) + (__ffs(msk) - 1);
                    if (i >= M) break;
                    u32 rw = (lane < Wd) ? mask[i * mwords + lane] : 0u;
                    kw &= ~rw;
                    i += 1;
                }
                if (lane < Wd) sm.nms.keepw[lane] = kw;
            }
            __syncthreads();

            // ---- block-scan append + incremental global histogram ----
            if (tid == 0) {
                int run = 0;
                for (int w = 0; w < Wd; w++) {
                    sm.nms.wpfx[w] = run;
                    run += __popc(sm.nms.keepw[w]);
                }
                sm.nms.wpfx[Wd] = run;
                sm.nms.base = atomicAdd(&g_count, run);
            }
            __syncthreads();
            const int base = sm.nms.base;

            for (int j = tid; j < M; j += NTHREADS) {
                u32 kwj = sm.nms.keepw[j >> 5];
                if ((kwj >> (j & 31)) & 1u) {
                    int rank = sm.nms.wpfx[j >> 5] + __popc(kwj & ((1u << (j & 31)) - 1u));
                    int pos = base + rank;
                    u64 kj = sm.nms.key[j];
                    u32 sb = (u32)(kj >> 32);
                    int key = bid * N_PROP + j;      // reference flat index
                    g_cscore[pos] = __uint_as_float(sb);
                    g_ckey[pos]   = key;
                    g_boxkey[key] = sm.nms.boxp[(int)(~(u32)kj)];
                    atomicAdd(&g_hist[score_bin(sb)], 1);
                }
            }
        }
    }

    // ---- completion: last block to arrive runs Phase C; others exit ----
    __threadfence();
    __syncthreads();
    if (tid == 0) {
        unsigned old = atomicInc(&g_done, NBLOCKS - 1);   // wraps -> self-reset
        s_last = (old == NBLOCKS - 1) ? 1 : 0;
    }
    __syncthreads();
    if (!s_last) return;
    __threadfence();

    // ================= Phase C: (last block) top-100 =================
    const int K = g_count;
    const int target = (K < DET_PER_IMG) ? K : DET_PER_IMG;

    if (tid == 0) { sm.topk.bstar = 0; sm.topk.cnt = 0; }
    __syncthreads();

    // chunk sums from global histogram (already built in Phase B)
    const int CH = NBINS / NTHREADS;        // 8
    const int base = tid * CH;
    int cs[CH];
    int sum = 0;
    #pragma unroll
    for (int t = 0; t < CH; t++) { cs[t] = g_hist[base + t]; sum += cs[t]; }

    // hierarchical suffix scan (3 syncs)
    int v = sum;
    #pragma unroll
    for (int off = 1; off < 32; off <<= 1) {
        int t = __shfl_down_sync(0xffffffffu, v, off);
        if (lane + off < 32) v += t;
    }
    if (lane == 0) sm.topk.part[wid] = v;     // warp totals (NWARPS entries)
    __syncthreads();
    if (tid < 32) {
        int wv = (lane < NWARPS) ? sm.topk.part[lane] : 0;
        #pragma unroll
        for (int off = 1; off < NWARPS; off <<= 1) {
            int t = __shfl_down_sync(0xffffffffu, wv, off);
            if (lane + off < NWARPS) wv += t;
        }
        if (lane < NWARPS) sm.topk.part[NWARPS + lane] = wv;   // suffix-incl warp totals
    }
    __syncthreads();
    {
        int after_warp = (wid < NWARPS - 1) ? sm.topk.part[NWARPS + wid + 1] : 0;
        int suf = (v - sum) + after_warp;     // chunks strictly after mine
        #pragma unroll
        for (int t = CH - 1; t >= 0; t--) {
            suf += cs[t];
            if (suf >= target) { atomicMax(&sm.topk.bstar, base + t); break; }
        }
    }
    __syncthreads();
    const int bstar = sm.topk.bstar;

    // compact candidates in bins >= b*
    for (int i = tid; i < K; i += NTHREADS) {
        u32 sb = __float_as_uint(g_cscore[i]);
        if (score_bin(sb) >= bstar) {
            int pos = atomicAdd(&sm.topk.cnt, 1);
            if (pos < TOPK_CAP)
                sm.topk.buf[pos] = ((u64)sb << 32) | (u32)(~g_ckey[i]);
        }
    }
    __syncthreads();
    const int C = sm.topk.cnt;

    if (C <= NTHREADS) {
        // register-resident hybrid bitonic, direct output
        int P2 = 32;
        while (P2 < C) P2 <<= 1;
        u64 v2 = (tid < C) ? sm.topk.buf[tid] : 0ULL;
        for (int k = 2; k <= P2; k <<= 1) {
            for (int j = k >> 1; j > 0; j >>= 1) {
                if (j >= 32) {
                    __syncthreads();
                    if (tid < P2) sm.topk.buf[tid] = v2;
                    __syncthreads();
                    if (tid < P2) {
                        u64 o = sm.topk.buf[tid ^ j];
                        bool takeMax = ((tid & k) == 0) == ((tid & j) == 0);
                        v2 = takeMax ? (v2 > o ? v2 : o) : (v2 < o ? v2 : o);
                    }
                } else {
                    u64 o = __shfl_xor_sync(0xffffffffu, v2, j);
                    bool takeMax = ((tid & k) == 0) == ((tid & j) == 0);
                    v2 = takeMax ? (v2 > o ? v2 : o) : (v2 < o ? v2 : o);
                }
            }
        }
        if (tid < DET_PER_IMG) {
            if (tid < C) {
                int key = (int)(~(u32)v2);
                float4 b = g_boxkey[key];
                out[tid] = __uint_as_float((u32)(v2 >> 32));
                out[DET_PER_IMG + tid * 4 + 0] = b.x;
                out[DET_PER_IMG + tid * 4 + 1] = b.y;
                out[DET_PER_IMG + tid * 4 + 2] = b.z;
                out[DET_PER_IMG + tid * 4 + 3] = b.w;
                out[DET_PER_IMG * 5 + tid] = (float)(key / N_PROP + 1);
            } else {
                out[tid] = 0.0f;
                out[DET_PER_IMG + tid * 4 + 0] = 0.0f;
                out[DET_PER_IMG + tid * 4 + 1] = 0.0f;
                out[DET_PER_IMG + tid * 4 + 2] = 0.0f;
                out[DET_PER_IMG + tid * 4 + 3] = 0.0f;
                out[DET_PER_IMG * 5 + tid] = 0.0f;
            }
        }
        return;
    }

    if (C <= TOPK_CAP) {
        // shared bitonic over up to 2048 elements
        int P2 = 1024;
        while (P2 < C) P2 <<= 1;
        for (int i = C + tid; i < P2; i += NTHREADS) sm.topk.buf[i] = 0ULL;
        __syncthreads();

        for (int k = 2; k <= P2; k <<= 1) {
            for (int j = k >> 1; j > 0; j >>= 1) {
                for (int i = tid; i < P2; i += NTHREADS) {
                    int ixj = i ^ j;
                    if (ixj > i) {
                        u64 a = sm.topk.buf[i], b = sm.topk.buf[ixj];
                        bool up = ((i & k) == 0);
                        if (up ? (a < b) : (a > b)) { sm.topk.buf[i] = b; sm.topk.buf[ixj] = a; }
                    }
                }
                __syncthreads();
            }
        }

        for (int r = tid; r < DET_PER_IMG; r += NTHREADS) {
            if (r < C) {
                u64 vv = sm.topk.buf[r];
                int key = (int)(~(u32)vv);
                float4 b = g_boxkey[key];
                out[r] = __uint_as_float((u32)(vv >> 32));
                out[DET_PER_IMG + r * 4 + 0] = b.x;
                out[DET_PER_IMG + r * 4 + 1] = b.y;
                out[DET_PER_IMG + r * 4 + 2] = b.z;
                out[DET_PER_IMG + r * 4 + 3] = b.w;
                out[DET_PER_IMG * 5 + r] = (float)(key / N_PROP + 1);
            } else {
                out[r] = 0.0f;
                out[DET_PER_IMG + r * 4 + 0] = 0.0f;
                out[DET_PER_IMG + r * 4 + 1] = 0.0f;
                out[DET_PER_IMG + r * 4 + 2] = 0.0f;
                out[DET_PER_IMG + r * 4 + 3] = 0.0f;
                out[DET_PER_IMG * 5 + r] = 0.0f;
            }
        }
        return;
    }

    // -------- fallback: repeated global argmax (C > TOPK_CAP, pathological) ------
    u64* r_v = sm.topk.buf;
    int* r_i = (int*)(sm.topk.buf + NTHREADS);
    __syncthreads();
    for (int r = 0; r < DET_PER_IMG; r++) {
        u64 bv = 0ULL; int bi = -1;
        for (int i = tid; i < K; i += NTHREADS) {
            u32 sb = __float_as_uint(g_cscore[i]);
            u64 vv = ((u64)sb << 32) | (u32)(~g_ckey[i]);
            if (vv > bv) { bv = vv; bi = i; }
        }
        r_v[tid] = bv; r_i[tid] = bi;
        __syncthreads();
        for (int off = NTHREADS >> 1; off > 0; off >>= 1) {
            if (tid < off) {
                if (r_v[tid + off] > r_v[tid]) { r_v[tid] = r_v[tid + off]; r_i[tid] = r_i[tid + off]; }
            }
            __syncthreads();
        }
        if (tid == 0) {
            int idx = r_i[0];
            u64 vv = r_v[0];
            int key = (int)(~(u32)vv);
            float4 b = g_boxkey[key];
            out[r] = __uint_as_float((u32)(vv >> 32));
            out[DET_PER_IMG + r * 4 + 0] = b.x;
            out[DET_PER_IMG + r * 4 + 1] = b.y;
            out[DET_PER_IMG + r * 4 + 2] = b.z;
            out[DET_PER_IMG + r * 4 + 3] = b.w;
            out[DET_PER_IMG * 5 + r] = (float)(key / N_PROP + 1);
            g_cscore[idx] = 0.0f;
        }
        __syncthreads();
    }
}

extern "C" void kernel_launch(void* const* d_in, const int* in_sizes, int n_in,
                              void* d_out, int out_size) {
    const float* logits = (const float*)d_in[0];   // [1000, 81]
    const float* deltas = (const float*)d_in[1];   // [1000, 324]
    const float* pboxes = (const float*)d_in[2];   // [1000, 4]
    const int*   ih     = (const int*)d_in[3];     // scalar
    const int*   iw     = (const int*)d_in[4];     // scalar

    fused_kernel<<<NBLOCKS, NTHREADS>>>(logits, deltas, pboxes, ih, iw, (float*)d_out);
}

// round 14
// speedup vs baseline: 1.4803x; 1.0009x over previous
#include <cuda_runtime.h>
#include <math.h>

#define N_PROP 1000
#define NUM_CLASSES 81
#define NUM_FG 80
#define SCORE_THRESH 0.05f
#define NMS_THRESH 0.5f
#define DET_PER_IMG 100
#define BBOX_XFORM_CLIP 4.135166556742356f
#define CAND_MAX (N_PROP * NUM_FG)

#define NBLOCKS 80
#define NTHREADS 512
#define NWARPS (NTHREADS / 32)

#define MROW 1024            // global-mask rows (fallback, M > 256)
#define MWORDS 32            // 1024 bits
#define MROW_SH 256          // shared-mask rows (fast path)
#define MWORDS_SH 8          // 256 bits

#define NBINS 4096
#define TOPK_CAP 2048

typedef unsigned long long u64;
typedef unsigned int u32;

// ---------- device scratch (no allocations allowed) ----------
__device__ float  g_lse[N_PROP];
__device__ int    g_count;
__device__ int    g_hist[NBINS];                       // global histogram (built in Phase B)
__device__ float  g_cscore[CAND_MAX];
__device__ int    g_ckey[CAND_MAX];
__device__ float4 g_boxkey[CAND_MAX];
__device__ u32    g_mask[NUM_FG * MROW * MWORDS];      // fallback mask (M > 256)

// barrier + completion counters (wrap -> self-reset across graph replays)
__device__ unsigned int g_bar_count = 0;
__device__ unsigned int g_bar_gen   = 0;
__device__ unsigned int g_done      = 0;

__device__ __forceinline__ void grid_sync() {
    __threadfence();
    __syncthreads();
    if (threadIdx.x == 0) {
        unsigned gen = *((volatile unsigned*)&g_bar_gen);
        unsigned old = atomicInc(&g_bar_count, NBLOCKS - 1);   // wraps to 0 -> self-reset
        if (old == NBLOCKS - 1) {
            atomicAdd(&g_bar_gen, 1);
        } else {
            while (*((volatile unsigned*)&g_bar_gen) == gen) {}
        }
    }
    __syncthreads();
    __threadfence();
}

__device__ __forceinline__ float load_dim(const int* p) {
    int vi = *p;
    if (vi > 0 && vi < 100000) return (float)vi;
    return __int_as_float(vi);
}

__device__ __forceinline__ int score_bin(u32 bits) {
    int b = (int)(bits >> 14) - 0xF400;      // scores in (0.05, 1] -> positive bins
    return min(NBINS - 1, max(0, b));
}

// ---------- shared memory union across phases ----------
struct SmemNMS {
    u64    key[1024];        // (score_bits<<32) | ~prop_idx
    float4 boxp[1024];       // box indexed by PROPOSAL id (no sort payload)
    u32    masksh[MROW_SH * MWORDS_SH];
    u32    keepw[MWORDS];
    int    wpfx[MWORDS + 1];
    int    base;
    int    cnt;
};
struct SmemTopk {
    u64 buf[TOPK_CAP];
    int part[NTHREADS];
    int bstar;
    int cnt;
};
union SmemAll {
    SmemNMS  nms;
    SmemTopk topk;
};

__global__ void __launch_bounds__(NTHREADS, 1)
fused_kernel(const float* __restrict__ logits,
             const float* __restrict__ deltas,
             const float* __restrict__ pboxes,
             const int* __restrict__ ih_p,
             const int* __restrict__ iw_p,
             float* __restrict__ out) {
    __shared__ SmemAll sm;
    __shared__ int s_last;
    const int tid  = threadIdx.x;
    const int bid  = blockIdx.x;
    const int lane = tid & 31;
    const int wid  = tid >> 5;

    // ====== Phase A: prefetch + per-proposal lse (warp per proposal) ======
    if (bid == 0 && tid == 0) g_count = 0;
    {
        int z = bid * NTHREADS + tid;
        if (z < NBINS) g_hist[z] = 0;
    }
    {
        // issue-only L2 prefetch of deltas + pboxes (consumed in Phase B)
        int t = bid * NTHREADS + tid;                       // 0..40959
        const char* dbase = (const char*)deltas;
        if (t < (N_PROP * NUM_CLASSES * 16) / 128)          // 10125 lines
            asm volatile("prefetch.global.L2 [%0];" :: "l"(dbase + (size_t)t * 128));
        if (t < (N_PROP * 16) / 128)                        // 125 lines
            asm volatile("prefetch.global.L2 [%0];" :: "l"((const char*)pboxes + (size_t)t * 128));
    }
    {
        const int p = bid * NWARPS + wid;                   // 0..1279: single pass
        if (p < N_PROP) {
            const float* row = logits + p * NUM_CLASSES;
            float v0 = row[lane];
            float v1 = row[lane + 32];
            bool has2 = (lane + 64 < NUM_CLASSES);
            float v2 = has2 ? row[lane + 64] : -INFINITY;
            float m = fmaxf(fmaxf(v0, v1), v2);
            #pragma unroll
            for (int o = 16; o > 0; o >>= 1) m = fmaxf(m, __shfl_xor_sync(0xffffffffu, m, o));
            float s = expf(v0 - m) + expf(v1 - m);
            if (has2) s += expf(v2 - m);
            #pragma unroll
            for (int o = 16; o > 0; o >>= 1) s += __shfl_xor_sync(0xffffffffu, s, o);
            if (lane == 0) g_lse[p] = m + logf(s);
        }
    }
    grid_sync();

    // ================= Phase B: per-class decode + sort + NMS =================
    {
        const int c = bid + 1;               // foreground class 1..80
        if (tid == 0) sm.nms.cnt = 0;
        __syncthreads();

        const float W = load_dim(iw_p) - 1.0f;
        const float H = load_dim(ih_p) - 1.0f;
        const float4* pb4 = (const float4*)pboxes;
        const float4* dl4 = (const float4*)deltas;

        for (int p = tid; p < N_PROP; p += NTHREADS) {
            float lg  = logits[p * NUM_CLASSES + c];   // strided, L2-hot after A
            float lse = g_lse[p];                      // coalesced
            float4 pb = pb4[p];                        // independent -> parallel
            float4 d  = dl4[p * NUM_CLASSES + c];      // independent -> parallel
            float sc = expf(lg - lse);
            if (sc > SCORE_THRESH) {
                float w  = pb.z - pb.x + 1.0f,  h  = pb.w - pb.y + 1.0f;
                float cx = pb.x + 0.5f * w,     cy = pb.y + 0.5f * h;
                float dx = d.x / 10.0f;
                float dy = d.y / 10.0f;
                float dw = fminf(d.z / 5.0f, BBOX_XFORM_CLIP);
                float dh = fminf(d.w / 5.0f, BBOX_XFORM_CLIP);
                float pcx = dx * w + cx, pcy = dy * h + cy;
                float pw  = expf(dw) * w, ph = expf(dh) * h;
                float bx1 = fminf(fmaxf(pcx - 0.5f * pw, 0.0f), W);
                float by1 = fminf(fmaxf(pcy - 0.5f * ph, 0.0f), H);
                float bx2 = fminf(fmaxf(pcx + 0.5f * pw - 1.0f, 0.0f), W);
                float by2 = fminf(fmaxf(pcy + 0.5f * ph - 1.0f, 0.0f), H);
                int slot = atomicAdd(&sm.nms.cnt, 1);
                sm.nms.key[slot] = ((u64)__float_as_uint(sc) << 32) | (u32)(~p);
                sm.nms.boxp[p]   = make_float4(bx1, by1, bx2, by2);
            }
        }
        __syncthreads();
        const int M = sm.nms.cnt;

        if (M > 0) {
            int P = 32;
            while (P < M) P <<= 1;

            if (P <= NTHREADS) {
                // ---- keys-only hybrid bitonic sort, register-resident ----
                u64 v = (tid < M) ? sm.nms.key[tid] : 0ULL;
                for (int k = 2; k <= P; k <<= 1) {
                    for (int j = k >> 1; j > 0; j >>= 1) {
                        if (j >= 32) {
                            __syncthreads();
                            if (tid < P) sm.nms.key[tid] = v;
                            __syncthreads();
                            if (tid < P) {
                                u64 o = sm.nms.key[tid ^ j];
                                bool takeMax = ((tid & k) == 0) == ((tid & j) == 0);
                                v = takeMax ? (v > o ? v : o) : (v < o ? v : o);
                            }
                        } else {
                            u64 o = __shfl_xor_sync(0xffffffffu, v, j);
                            bool takeMax = ((tid & k) == 0) == ((tid & j) == 0);
                            v = takeMax ? (v > o ? v : o) : (v < o ? v : o);
                        }
                    }
                }
                __syncthreads();
                if (tid < P) sm.nms.key[tid] = v;
                __syncthreads();
            } else {
                // ---- fallback: shared keys-only bitonic (M > NTHREADS, rare) ----
                for (int i = M + tid; i < P; i += NTHREADS) sm.nms.key[i] = 0ULL;
                __syncthreads();
                for (int k = 2; k <= P; k <<= 1) {
                    for (int j = k >> 1; j > 0; j >>= 1) {
                        for (int i = tid; i < P; i += NTHREADS) {
                            int ixj = i ^ j;
                            if (ixj > i) {
                                u64 a = sm.nms.key[i], b = sm.nms.key[ixj];
                                bool up = ((i & k) == 0);
                                if (up ? (a < b) : (a > b)) { sm.nms.key[i] = b; sm.nms.key[ixj] = a; }
                            }
                        }
                        __syncthreads();
                    }
                }
            }

            const bool shpath = (M <= MROW_SH);
            const int mwords = shpath ? MWORDS_SH : MWORDS;
            u32* mask = shpath ? sm.nms.masksh : &g_mask[bid * MROW * MWORDS];
            const int Wd = (M + 31) >> 5;

            // ---- ballot mask build: warp per row ----
            for (int i = wid; i < M; i += NWARPS) {
                u64 ki = sm.nms.key[i];
                int pi = (int)(~(u32)ki);
                float4 bi = sm.nms.boxp[pi];
                float ai = (bi.z - bi.x + 1.0f) * (bi.w - bi.y + 1.0f);
                int w0 = (i + 1) >> 5;
                if (lane < w0) mask[i * mwords + lane] = 0;
                for (int w = w0; w < Wd; w++) {
                    int j = (w << 5) + lane;
                    bool hit = false;
                    if (j > i && j < M) {
                        u64 kj = sm.nms.key[j];
                        int pj = (int)(~(u32)kj);
                        float4 bj = sm.nms.boxp[pj];
                        float lx = fmaxf(bi.x, bj.x), ly = fmaxf(bi.y, bj.y);
                        float rx = fminf(bi.z, bj.z), ry = fminf(bi.w, bj.w);
                        float iw = fmaxf(rx - lx + 1.0f, 0.0f);
                        float ih = fmaxf(ry - ly + 1.0f, 0.0f);
                        float inter = iw * ih;
                        float aj = (bj.z - bj.x + 1.0f) * (bj.w - bj.y + 1.0f);
                        hit = (inter / (ai + aj - inter) > NMS_THRESH);
                    }
                    u32 bits = __ballot_sync(0xffffffffu, hit);
                    if (lane == 0) mask[i * mwords + w] = bits;
                }
            }
            __syncthreads();

            // ---- greedy resolve: warp 0, skip dead boxes via ffs ----
            if (tid < 32) {
                u32 kw = (lane < Wd) ? 0xffffffffu : 0u;
                int rem = M & 31;
                if (rem && lane == Wd - 1) kw = (1u << rem) - 1u;
                int i = 0;
                while (i < M) {
                    u32 w = __shfl_sync(0xffffffffu, kw, i >> 5);
                    u32 msk = w & (0xffffffffu << (i & 31));
                    if (msk == 0) { i = ((i >> 5) + 1) << 5; continue; }
                    i = ((i >> 5) << 5) + (__ffs(msk) - 1);
                    if (i >= M) break;
                    u32 rw = (lane < Wd) ? mask[i * mwords + lane] : 0u;
                    kw &= ~rw;
                    i += 1;
                }
                if (lane < Wd) sm.nms.keepw[lane] = kw;
            }
            __syncthreads();

            // ---- block-scan append + incremental global histogram ----
            if (tid == 0) {
                int run = 0;
                for (int w = 0; w < Wd; w++) {
                    sm.nms.wpfx[w] = run;
                    run += __popc(sm.nms.keepw[w]);
                }
                sm.nms.wpfx[Wd] = run;
                sm.nms.base = atomicAdd(&g_count, run);
            }
            __syncthreads();
            const int base = sm.nms.base;

            for (int j = tid; j < M; j += NTHREADS) {
                u32 kwj = sm.nms.keepw[j >> 5];
                if ((kwj >> (j & 31)) & 1u) {
                    int rank = sm.nms.wpfx[j >> 5] + __popc(kwj & ((1u << (j & 31)) - 1u));
                    int pos = base + rank;
                    u64 kj = sm.nms.key[j];
                    u32 sb = (u32)(kj >> 32);
                    int key = bid * N_PROP + j;      // reference flat index
                    g_cscore[pos] = __uint_as_float(sb);
                    g_ckey[pos]   = key;
                    g_boxkey[key] = sm.nms.boxp[(int)(~(u32)kj)];
                    atomicAdd(&g_hist[score_bin(sb)], 1);
                }
            }
        }
    }

    // ---- completion: last block to arrive runs Phase C; others exit ----
    __threadfence();
    __syncthreads();
    if (tid == 0) {
        unsigned old = atomicInc(&g_done, NBLOCKS - 1);   // wraps -> self-reset
        s_last = (old == NBLOCKS - 1) ? 1 : 0;
    }
    __syncthreads();
    if (!s_last) return;
    __threadfence();

    // ================= Phase C: (last block) top-100 =================
    const int K = g_count;
    const int target = (K < DET_PER_IMG) ? K : DET_PER_IMG;

    if (tid == 0) { sm.topk.bstar = 0; sm.topk.cnt = 0; }
    __syncthreads();

    // chunk sums from global histogram (already built in Phase B)
    const int CH = NBINS / NTHREADS;        // 8
    const int base = tid * CH;
    int cs[CH];
    int sum = 0;
    #pragma unroll
    for (int t = 0; t < CH; t++) { cs[t] = g_hist[base + t]; sum += cs[t]; }

    // hierarchical suffix scan (3 syncs)
    int v = sum;
    #pragma unroll
    for (int off = 1; off < 32; off <<= 1) {
        int t = __shfl_down_sync(0xffffffffu, v, off);
        if (lane + off < 32) v += t;
    }
    if (lane == 0) sm.topk.part[wid] = v;     // warp totals (NWARPS entries)
    __syncthreads();
    if (tid < 32) {
        int wv = (lane < NWARPS) ? sm.topk.part[lane] : 0;
        #pragma unroll
        for (int off = 1; off < NWARPS; off <<= 1) {
            int t = __shfl_down_sync(0xffffffffu, wv, off);
            if (lane + off < NWARPS) wv += t;
        }
        if (lane < NWARPS) sm.topk.part[NWARPS + lane] = wv;   // suffix-incl warp totals
    }
    __syncthreads();
    {
        int after_warp = (wid < NWARPS - 1) ? sm.topk.part[NWARPS + wid + 1] : 0;
        int suf = (v - sum) + after_warp;     // chunks strictly after mine
        #pragma unroll
        for (int t = CH - 1; t >= 0; t--) {
            suf += cs[t];
            if (suf >= target) { atomicMax(&sm.topk.bstar, base + t); break; }
        }
    }
    __syncthreads();
    const int bstar = sm.topk.bstar;

    // compact candidates in bins >= b*
    for (int i = tid; i < K; i += NTHREADS) {
        u32 sb = __float_as_uint(g_cscore[i]);
        if (score_bin(sb) >= bstar) {
            int pos = atomicAdd(&sm.topk.cnt, 1);
            if (pos < TOPK_CAP)
                sm.topk.buf[pos] = ((u64)sb << 32) | (u32)(~g_ckey[i]);
        }
    }
    __syncthreads();
    const int C = sm.topk.cnt;

    if (C <= NTHREADS) {
        // register-resident hybrid bitonic, direct output
        int P2 = 32;
        while (P2 < C) P2 <<= 1;
        u64 v2 = (tid < C) ? sm.topk.buf[tid] : 0ULL;
        for (int k = 2; k <= P2; k <<= 1) {
            for (int j = k >> 1; j > 0; j >>= 1) {
                if (j >= 32) {
                    __syncthreads();
                    if (tid < P2) sm.topk.buf[tid] = v2;
                    __syncthreads();
                    if (tid < P2) {
                        u64 o = sm.topk.buf[tid ^ j];
                        bool takeMax = ((tid & k) == 0) == ((tid & j) == 0);
                        v2 = takeMax ? (v2 > o ? v2 : o) : (v2 < o ? v2 : o);
                    }
                } else {
                    u64 o = __shfl_xor_sync(0xffffffffu, v2, j);
                    bool takeMax = ((tid & k) == 0) == ((tid & j) == 0);
                    v2 = takeMax ? (v2 > o ? v2 : o) : (v2 < o ? v2 : o);
                }
            }
        }
        if (tid < DET_PER_IMG) {
            if (tid < C) {
                int key = (int)(~(u32)v2);
                float4 b = g_boxkey[key];
                out[tid] = __uint_as_float((u32)(v2 >> 32));
                out[DET_PER_IMG + tid * 4 + 0] = b.x;
                out[DET_PER_IMG + tid * 4 + 1] = b.y;
                out[DET_PER_IMG + tid * 4 + 2] = b.z;
                out[DET_PER_IMG + tid * 4 + 3] = b.w;
                out[DET_PER_IMG * 5 + tid] = (float)(key / N_PROP + 1);
            } else {
                out[tid] = 0.0f;
                out[DET_PER_IMG + tid * 4 + 0] = 0.0f;
                out[DET_PER_IMG + tid * 4 + 1] = 0.0f;
                out[DET_PER_IMG + tid * 4 + 2] = 0.0f;
                out[DET_PER_IMG + tid * 4 + 3] = 0.0f;
                out[DET_PER_IMG * 5 + tid] = 0.0f;
            }
        }
        return;
    }

    if (C <= TOPK_CAP) {
        // shared bitonic over up to 2048 elements
        int P2 = 1024;
        while (P2 < C) P2 <<= 1;
        for (int i = C + tid; i < P2; i += NTHREADS) sm.topk.buf[i] = 0ULL;
        __syncthreads();

        for (int k = 2; k <= P2; k <<= 1) {
            for (int j = k >> 1; j > 0; j >>= 1) {
                for (int i = tid; i < P2; i += NTHREADS) {
                    int ixj = i ^ j;
                    if (ixj > i) {
                        u64 a = sm.topk.buf[i], b = sm.topk.buf[ixj];
                        bool up = ((i & k) == 0);
                        if (up ? (a < b) : (a > b)) { sm.topk.buf[i] = b; sm.topk.buf[ixj] = a; }
                    }
                }
                __syncthreads();
            }
        }

        for (int r = tid; r < DET_PER_IMG; r += NTHREADS) {
            if (r < C) {
                u64 vv = sm.topk.buf[r];
                int key = (int)(~(u32)vv);
                float4 b = g_boxkey[key];
                out[r] = __uint_as_float((u32)(vv >> 32));
                out[DET_PER_IMG + r * 4 + 0] = b.x;
                out[DET_PER_IMG + r * 4 + 1] = b.y;
                out[DET_PER_IMG + r * 4 + 2] = b.z;
                out[DET_PER_IMG + r * 4 + 3] = b.w;
                out[DET_PER_IMG * 5 + r] = (float)(key / N_PROP + 1);
            } else {
                out[r] = 0.0f;
                out[DET_PER_IMG + r * 4 + 0] = 0.0f;
                out[DET_PER_IMG + r * 4 + 1] = 0.0f;
                out[DET_PER_IMG + r * 4 + 2] = 0.0f;
                out[DET_PER_IMG + r * 4 + 3] = 0.0f;
                out[DET_PER_IMG * 5 + r] = 0.0f;
            }
        }
        return;
    }

    // -------- fallback: repeated global argmax (C > TOPK_CAP, pathological) ------
    u64* r_v = sm.topk.buf;
    int* r_i = (int*)(sm.topk.buf + NTHREADS);
    __syncthreads();
    for (int r = 0; r < DET_PER_IMG; r++) {
        u64 bv = 0ULL; int bi = -1;
        for (int i = tid; i < K; i += NTHREADS) {
            u32 sb = __float_as_uint(g_cscore[i]);
            u64 vv = ((u64)sb << 32) | (u32)(~g_ckey[i]);
            if (vv > bv) { bv = vv; bi = i; }
        }
        r_v[tid] = bv; r_i[tid] = bi;
        __syncthreads();
        for (int off = NTHREADS >> 1; off > 0; off >>= 1) {
            if (tid < off) {
                if (r_v[tid + off] > r_v[tid]) { r_v[tid] = r_v[tid + off]; r_i[tid] = r_i[tid + off]; }
            }
            __syncthreads();
        }
        if (tid == 0) {
            int idx = r_i[0];
            u64 vv = r_v[0];
            int key = (int)(~(u32)vv);
            float4 b = g_boxkey[key];
            out[r] = __uint_as_float((u32)(vv >> 32));
            out[DET_PER_IMG + r * 4 + 0] = b.x;
            out[DET_PER_IMG + r * 4 + 1] = b.y;
            out[DET_PER_IMG + r * 4 + 2] = b.z;
            out[DET_PER_IMG + r * 4 + 3] = b.w;
            out[DET_PER_IMG * 5 + r] = (float)(key / N_PROP + 1);
            g_cscore[idx] = 0.0f;
        }
        __syncthreads();
    }
}

extern "C" void kernel_launch(void* const* d_in, const int* in_sizes, int n_in,
                              void* d_out, int out_size) {
    const float* logits = (const float*)d_in[0];   // [1000, 81]
    const float* deltas = (const float*)d_in[1];   // [1000, 324]
    const float* pboxes = (const float*)d_in[2];   // [1000, 4]
    const int*   ih     = (const int*)d_in[3];     // scalar
    const int*   iw     = (const int*)d_in[4];     // scalar

    fused_kernel<<<NBLOCKS, NTHREADS>>>(logits, deltas, pboxes, ih, iw, (float*)d_out);
}